// round 7
// baseline (speedup 1.0000x reference)
#include <cuda_runtime.h>
#include <cuda_bf16.h>
#include <cstdint>

#define BSZ 2
#define LSEQ 1024
#define DM 768
#define DI 1536
#define DS 16
#define DC 4
#define DTR 48
#define NL 24
#define RWS (BSZ*LSEQ)
#define DBLW (DTR + 2*DS)       /* 80 */
#define EPSF 1e-5f
#define XP_SLICES 8
#define XP_KLEN (DI/XP_SLICES)  /* 192 */

// ---------------------------------------------------------------------------
// f32 buffers
// ---------------------------------------------------------------------------
__device__ float g_x[2][RWS*DM];
__device__ float g_xz[2][RWS*2*DI];
__device__ float g_xc[2][RWS*DI];
__device__ float g_dbl[2][RWS*DBLW];
__device__ float g_delta[2][RWS*DI];
__device__ float g_y[2][RWS*DI];
__device__ float g_xp_part[2][XP_SLICES][RWS*128];

// int8 activations (2-digit) + per-row scales
__device__ int8_t a_h1[2][RWS*DM],   a_h2[2][RWS*DM];
__device__ int8_t a_xc1[2][RWS*DI],  a_xc2[2][RWS*DI];
__device__ int8_t a_db1[2][RWS*DTR], a_db2[2][RWS*DTR];
__device__ int8_t a_y1[2][RWS*DI],   a_y2[2][RWS*DI];
__device__ float  s_h[2][RWS], s_xc[2][RWS], s_db[2][RWS], s_y[2][RWS];

// int8 weights (2-digit) + per-outrow scales
__device__ int8_t w_ip1[2][NL*2*DI*DM], w_ip2[2][NL*2*DI*DM];
__device__ int8_t w_op1[2][NL*DM*DI],   w_op2[2][NL*DM*DI];
__device__ int8_t w_xp1[2][NL*DBLW*DI], w_xp2[2][NL*DBLW*DI];
__device__ int8_t w_dt1[2][NL*DI*DTR],  w_dt2[2][NL*DI*DTR];
__device__ float  s_wip[2][NL*2*DI], s_wop[2][NL*DM], s_wxp[2][NL*DBLW], s_wdt[2][NL*DI];

// ---------------------------------------------------------------------------
// helpers
// ---------------------------------------------------------------------------
__device__ __forceinline__ uint32_t smem_u32(const void* p) {
    uint32_t a;
    asm("{ .reg .u64 t; cvta.to.shared.u64 t, %1; cvt.u32.u64 %0, t; }" : "=r"(a) : "l"(p));
    return a;
}

// u in [-127,127]: q1 = round(u), q2 = round((u-q1)*256) clamped
__device__ __forceinline__ void quant2u(float u, int8_t* q1p, int8_t* q2p) {
    float q1 = rintf(u);
    float q2 = rintf((u - q1) * 256.f);
    q2 = fminf(fmaxf(q2, -127.f), 127.f);
    *q1p = (int8_t)(int)q1;
    *q2p = (int8_t)(int)q2;
}

#define CP16(dst, src, sz) \
    asm volatile("cp.async.cg.shared.global [%0], [%1], 16, %2;" \
        :: "r"(dst), "l"(src), "r"(sz) : "memory")
#define CP_COMMIT() asm volatile("cp.async.commit_group;" ::: "memory")
#define CP_WAIT1()  asm volatile("cp.async.wait_group 1;" ::: "memory")
#define CP_WAIT0()  asm volatile("cp.async.wait_group 0;" ::: "memory")

#define LDSM4(r, addr) \
    asm volatile("ldmatrix.sync.aligned.m8n8.x4.shared.b16 {%0,%1,%2,%3}, [%4];" \
        : "=r"((r)[0]), "=r"((r)[1]), "=r"((r)[2]), "=r"((r)[3]) : "r"(addr))

#define IMMA16832(c, a, b0v, b1v) \
    asm volatile("mma.sync.aligned.m16n8k32.row.col.s32.s8.s8.s32 " \
        "{%0,%1,%2,%3}, {%4,%5,%6,%7}, {%8,%9}, {%0,%1,%2,%3};" \
        : "+r"((c)[0]), "+r"((c)[1]), "+r"((c)[2]), "+r"((c)[3]) \
        : "r"((a)[0]), "r"((a)[1]), "r"((a)[2]), "r"((a)[3]), "r"(b0v), "r"(b1v))

// ---------------------------------------------------------------------------
// Weight quantization: per-row 2-digit int8
// ---------------------------------------------------------------------------
__global__ __launch_bounds__(128)
void k_wquant(const float* __restrict__ sF, const float* __restrict__ sB,
              int8_t* q1F, int8_t* q2F, float* scF,
              int8_t* q1B, int8_t* q2B, float* scB, int K) {
    int row = blockIdx.x, dir = blockIdx.y;
    const float* src = (dir ? sB : sF) + (size_t)row * K;
    int8_t* q1 = (dir ? q1B : q1F) + (size_t)row * K;
    int8_t* q2 = (dir ? q2B : q2F) + (size_t)row * K;
    float* sc = dir ? scB : scF;
    float mx = 0.f;
    for (int i = threadIdx.x; i < K; i += 128) mx = fmaxf(mx, fabsf(src[i]));
    #pragma unroll
    for (int o = 16; o; o >>= 1) mx = fmaxf(mx, __shfl_xor_sync(0xffffffffu, mx, o));
    __shared__ float sm[4];
    if ((threadIdx.x & 31) == 0) sm[threadIdx.x >> 5] = mx;
    __syncthreads();
    mx = fmaxf(fmaxf(sm[0], sm[1]), fmaxf(sm[2], sm[3]));
    float inv = (mx > 0.f) ? 127.f / mx : 0.f;
    if (threadIdx.x == 0) sc[row] = mx * (1.f/127.f);
    for (int i = threadIdx.x; i < K; i += 128)
        quant2u(src[i] * inv, q1 + i, q2 + i);
}

// ---------------------------------------------------------------------------
// Embedding
// ---------------------------------------------------------------------------
__global__ void k_embed(const int* __restrict__ ids,
                        const float* __restrict__ embF,
                        const float* __restrict__ embB) {
    int row = blockIdx.x, dir = blockIdx.y;
    int b = row / LSEQ, l = row % LSEQ;
    int tok = (dir == 0) ? ids[b*LSEQ + l] : ids[b*LSEQ + (LSEQ-1-l)];
    const float* emb = (dir == 0) ? embF : embB;
    const float4* src = (const float4*)(emb + (size_t)tok * DM);
    float4* dst = (float4*)(g_x[dir] + (size_t)row * DM);
    for (int i = threadIdx.x; i < DM/4; i += blockDim.x) dst[i] = src[i];
}

// ---------------------------------------------------------------------------
// RMSNorm -> int8 2-digit
// ---------------------------------------------------------------------------
__global__ __launch_bounds__(256)
void k_rmsnorm(const float* __restrict__ wF, const float* __restrict__ wB) {
    __shared__ float cache[DM];
    __shared__ float red1[8];
    __shared__ float red2[8];
    int row = blockIdx.x, dir = blockIdx.y;
    const float* x = g_x[dir] + (size_t)row * DM;
    const float* w = dir ? wB : wF;
    int tid = threadIdx.x, lane = tid & 31, wid = tid >> 5;
    float s = 0.f;
    for (int i = tid; i < DM; i += 256) { float v = x[i]; s += v*v; }
    #pragma unroll
    for (int o = 16; o; o >>= 1) s += __shfl_xor_sync(0xffffffffu, s, o);
    if (lane == 0) red1[wid] = s;
    __syncthreads();
    s = red1[0]+red1[1]+red1[2]+red1[3]+red1[4]+red1[5]+red1[6]+red1[7];
    float invr = rsqrtf(s / (float)DM + EPSF);
    float mx = 0.f;
    for (int i = tid; i < DM; i += 256) {
        float v = x[i] * invr * w[i];
        cache[i] = v;
        mx = fmaxf(mx, fabsf(v));
    }
    #pragma unroll
    for (int o = 16; o; o >>= 1) mx = fmaxf(mx, __shfl_xor_sync(0xffffffffu, mx, o));
    if (lane == 0) red2[wid] = mx;
    __syncthreads();
    mx = fmaxf(fmaxf(fmaxf(red2[0],red2[1]),fmaxf(red2[2],red2[3])),
               fmaxf(fmaxf(red2[4],red2[5]),fmaxf(red2[6],red2[7])));
    float inv = (mx > 0.f) ? 127.f / mx : 0.f;
    if (tid == 0) s_h[dir][row] = mx * (1.f/127.f);
    size_t base = (size_t)row * DM;
    for (int i = tid; i < DM; i += 256)
        quant2u(cache[i] * inv, &a_h1[dir][base+i], &a_h2[dir][base+i]);
}

// ---------------------------------------------------------------------------
// int8 split GEMM: C[m,n] = sA[m]*sW[n]*(q1p1 + (q1p2+q2p1)/256)
// 512 threads, 16 warps (4Mx4N), warp tile 32x32, CTA 128x128, K chunk 64.
// Stage: TileA(128x128B: q1|q2) + TileW(128x128B: p1|p2) = 32KB, double buf.
// ---------------------------------------------------------------------------
#define GTK 64
#define TILE_I8 16384
#define STAGE_B 32768
#define GEMM_SMEM (2*STAGE_B)

__device__ __forceinline__ void stage_i8(
    uint32_t stg,
    const int8_t* __restrict__ A1, const int8_t* __restrict__ A2, int lda,
    const int8_t* __restrict__ W1, const int8_t* __restrict__ W2, int ldw,
    int m0, int n0, int k0, int N, int K, int tid)
{
    #pragma unroll
    for (int t = 0; t < 4; t++) {
        int idx = tid + t*512;            // 0..2047
        int tile = idx >> 10;             // 0=A, 1=W
        int r = (idx >> 3) & 127;
        int col = idx & 7;
        int kk = k0 + ((col & 3) << 4);
        uint32_t sw = (uint32_t)((col*16) ^ ((r & 7) << 4));
        uint32_t soff = (uint32_t)(tile*TILE_I8 + r*128) + sw;
        const int8_t* base;
        int valid;
        size_t goff;
        if (tile == 0) {
            base = (col < 4) ? A1 : A2;
            valid = (kk < K);
            goff = (size_t)(m0 + r) * lda + kk;
        } else {
            base = (col < 4) ? W1 : W2;
            valid = (kk < K) && (n0 + r < N);
            goff = (size_t)(n0 + r) * ldw + kk;
        }
        CP16(stg + soff, base + (valid ? goff : 0), valid ? 16 : 0);
    }
}

__device__ __forceinline__ void i8_step(
    uint32_t Ab, uint32_t Wb, int ka, int kw,
    const uint32_t* aOff, const uint32_t* aMsk,
    const uint32_t* bOff, const uint32_t* bMsk,
    int a_kbx, int b_kbx, int ic[2][4][4])
{
    uint32_t aa[2][4], bb[2][4];
    #pragma unroll
    for (int mt = 0; mt < 2; mt++)
        LDSM4(aa[mt], Ab + aOff[mt] + (uint32_t)(((uint32_t)(ka + a_kbx)) ^ aMsk[mt]));
    #pragma unroll
    for (int g = 0; g < 2; g++)
        LDSM4(bb[g], Wb + bOff[g] + (uint32_t)(((uint32_t)(kw + b_kbx)) ^ bMsk[g]));
    #pragma unroll
    for (int mt = 0; mt < 2; mt++)
        #pragma unroll
        for (int nt = 0; nt < 4; nt++) {
            int g = nt >> 1, o = (nt & 1) * 2;
            IMMA16832(ic[mt][nt], aa[mt], bb[g][o], bb[g][o+1]);
        }
}

__global__ __launch_bounds__(512, 1)
void k_gemm(int aId, int lda,
            const int8_t* __restrict__ W1d0, const int8_t* __restrict__ W2d0,
            const float* __restrict__ sW0,
            const int8_t* __restrict__ W1d1, const int8_t* __restrict__ W2d1,
            const float* __restrict__ sW1,
            int cfId, float* __restrict__ outp,
            int M, int N, int K,
            const float* __restrict__ b0, const float* __restrict__ b1,
            int epi, int splitK, float* __restrict__ partial)
{
    extern __shared__ __align__(1024) char smem[];
    const int dir = blockIdx.z;
    const int8_t *A1, *A2; const float* sA;
    switch (aId) {
        case 0:  A1 = a_h1[dir];  A2 = a_h2[dir];  sA = s_h[dir];  break;
        case 1:  A1 = a_xc1[dir]; A2 = a_xc2[dir]; sA = s_xc[dir]; break;
        case 2:  A1 = a_db1[dir]; A2 = a_db2[dir]; sA = s_db[dir]; break;
        default: A1 = a_y1[dir];  A2 = a_y2[dir];  sA = s_y[dir];  break;
    }
    const int8_t* W1 = dir ? W1d1 : W1d0;
    const int8_t* W2 = dir ? W2d1 : W2d0;
    const float* sW = dir ? sW1 : sW0;
    const float* bias = dir ? b1 : b0;

    const uint32_t tb = smem_u32(smem);
    const int tid = threadIdx.x, lane = tid & 31, wid = tid >> 5;
    const int wm = wid & 3, wn = wid >> 2;
    const int m0 = blockIdx.y * 128;
    int n0, kbase, kLen, slice = 0;
    if (splitK) { slice = blockIdx.x; n0 = 0; kLen = XP_KLEN; kbase = slice * XP_KLEN; }
    else        { n0 = blockIdx.x * 128; kLen = K; kbase = 0; }

    const int l15 = lane & 15;
    const int a_kbx = (lane & 16) ? 16 : 0;
    const int b_nrow = (lane & 7) + ((lane & 16) ? 8 : 0);
    const int b_kbx = (lane & 8) ? 16 : 0;

    uint32_t aOff[2], aMsk[2];
    #pragma unroll
    for (int mt = 0; mt < 2; mt++) {
        int r = wm*32 + mt*16 + l15;
        aOff[mt] = r * 128;
        aMsk[mt] = (r & 7) << 4;
    }
    uint32_t bOff[2], bMsk[2];
    #pragma unroll
    for (int g = 0; g < 2; g++) {
        int r = wn*32 + g*16 + b_nrow;
        bOff[g] = r * 128;
        bMsk[g] = (r & 7) << 4;
    }

    float cf[2][4][4];
    #pragma unroll
    for (int i = 0; i < 2; i++)
        #pragma unroll
        for (int j = 0; j < 4; j++)
            #pragma unroll
            for (int q = 0; q < 4; q++) cf[i][j][q] = 0.f;

    const int nch = (kLen + GTK - 1) / GTK;
    stage_i8(tb, A1, A2, lda, W1, W2, K, m0, n0, kbase, N, K, tid);
    CP_COMMIT();

    for (int ch = 0; ch < nch; ch++) {
        if (ch + 1 < nch) {
            stage_i8(tb + ((ch+1)&1)*STAGE_B, A1, A2, lda, W1, W2, K,
                     m0, n0, kbase + (ch+1)*GTK, N, K, tid);
            CP_COMMIT();
            CP_WAIT1();
        } else {
            CP_WAIT0();
        }
        __syncthreads();

        const uint32_t Ab = tb + (ch&1)*STAGE_B;
        const uint32_t Wb = Ab + TILE_I8;
        int ic[2][4][4];

        // ---- MAIN: q1*p1 ----
        #pragma unroll
        for (int i = 0; i < 2; i++)
            #pragma unroll
            for (int j = 0; j < 4; j++)
                #pragma unroll
                for (int q = 0; q < 4; q++) ic[i][j][q] = 0;
        i8_step(Ab, Wb, 0, 0,  aOff, aMsk, bOff, bMsk, a_kbx, b_kbx, ic);
        i8_step(Ab, Wb, 32, 32, aOff, aMsk, bOff, bMsk, a_kbx, b_kbx, ic);
        #pragma unroll
        for (int i = 0; i < 2; i++)
            #pragma unroll
            for (int j = 0; j < 4; j++)
                #pragma unroll
                for (int q = 0; q < 4; q++) cf[i][j][q] += (float)ic[i][j][q];

        // ---- CROSS: q1*p2 + q2*p1 (scale 1/256) ----
        #pragma unroll
        for (int i = 0; i < 2; i++)
            #pragma unroll
            for (int j = 0; j < 4; j++)
                #pragma unroll
                for (int q = 0; q < 4; q++) ic[i][j][q] = 0;
        i8_step(Ab, Wb, 0,  64, aOff, aMsk, bOff, bMsk, a_kbx, b_kbx, ic);
        i8_step(Ab, Wb, 32, 96, aOff, aMsk, bOff, bMsk, a_kbx, b_kbx, ic);
        i8_step(Ab, Wb, 64, 0,  aOff, aMsk, bOff, bMsk, a_kbx, b_kbx, ic);
        i8_step(Ab, Wb, 96, 32, aOff, aMsk, bOff, bMsk, a_kbx, b_kbx, ic);
        #pragma unroll
        for (int i = 0; i < 2; i++)
            #pragma unroll
            for (int j = 0; j < 4; j++)
                #pragma unroll
                for (int q = 0; q < 4; q++) cf[i][j][q] += (float)ic[i][j][q] * (1.f/256.f);

        __syncthreads();
    }

    // ---- epilogue: dequant + (bias/softplus) + store ----
    const int mrow = m0 + wm*32 + (lane >> 2);
    const int nl0 = wn*32 + (lane & 3)*2;
    if (splitK) {
        float* pbase = partial + ((size_t)(dir*XP_SLICES + slice))*RWS*128;
        #pragma unroll
        for (int mt = 0; mt < 2; mt++)
            #pragma unroll
            for (int nt = 0; nt < 4; nt++) {
                int nl = nl0 + nt*8;
                int ns0 = (nl   < N) ? nl   : 0;
                int ns1 = (nl+1 < N) ? nl+1 : 0;
                float w0 = sW[ns0], w1 = sW[ns1];
                #pragma unroll
                for (int half = 0; half < 2; half++) {
                    int m = mrow + mt*16 + half*8;
                    float sa = sA[m];
                    *(float2*)(pbase + (size_t)m*128 + nl) =
                        make_float2(cf[mt][nt][half*2]*sa*w0, cf[mt][nt][half*2+1]*sa*w1);
                }
            }
        return;
    }
    float* Cf = (cfId == 1) ? g_xz[dir] : ((cfId == 4) ? g_delta[dir] : g_x[dir]);
    #pragma unroll
    for (int mt = 0; mt < 2; mt++) {
        #pragma unroll
        for (int nt = 0; nt < 4; nt++) {
            int n = n0 + nl0 + nt*8;
            if (n >= N) continue;
            float w0 = sW[n], w1 = sW[n+1];
            #pragma unroll
            for (int half = 0; half < 2; half++) {
                int m = mrow + mt*16 + half*8;
                float sa = sA[m];
                float v0 = cf[mt][nt][half*2+0] * sa * w0;
                float v1 = cf[mt][nt][half*2+1] * sa * w1;
                if (epi == 1) {
                    v0 += bias[n];   v1 += bias[n+1];
                    v0 = (v0 > 20.f) ? v0 : log1pf(__expf(v0));
                    v1 = (v1 > 20.f) ? v1 : log1pf(__expf(v1));
                }
                *(float2*)(Cf + (size_t)m*N + n) = make_float2(v0, v1);
                if (outp)
                    *(float2*)(outp + (size_t)m*(2*DM) + dir*DM + n) = make_float2(v0, v1);
            }
        }
    }
}

// ---------------------------------------------------------------------------
// Conv1d (k=4) + bias + SiLU, row-per-block -> f32 + int8 quant
// ---------------------------------------------------------------------------
__global__ __launch_bounds__(256)
void k_conv(const float* __restrict__ cwF, const float* __restrict__ cwB,
            const float* __restrict__ cbF, const float* __restrict__ cbB) {
    __shared__ float red2[8];
    int row = blockIdx.x, dir = blockIdx.y;
    int b = row / LSEQ, l = row % LSEQ;
    int tid = threadIdx.x, lane = tid & 31, wid = tid >> 5;
    const float* xz = g_xz[dir];
    const float* cwb = dir ? cwB : cwF;
    const float* cbb = dir ? cbB : cbF;
    float vv[6];
    float mx = 0.f;
    #pragma unroll
    for (int j = 0; j < 6; j++) {
        int c = tid + j*256;
        const float* cw = cwb + c*DC;
        float acc = cbb[c];
        #pragma unroll
        for (int k = 0; k < DC; k++) {
            int ls = l - (DC-1) + k;
            if (ls >= 0) acc += xz[(size_t)(b*LSEQ + ls)*2*DI + c] * cw[k];
        }
        float v = acc / (1.f + __expf(-acc));
        g_xc[dir][(size_t)row*DI + c] = v;
        vv[j] = v;
        mx = fmaxf(mx, fabsf(v));
    }
    #pragma unroll
    for (int o = 16; o; o >>= 1) mx = fmaxf(mx, __shfl_xor_sync(0xffffffffu, mx, o));
    if (lane == 0) red2[wid] = mx;
    __syncthreads();
    mx = fmaxf(fmaxf(fmaxf(red2[0],red2[1]),fmaxf(red2[2],red2[3])),
               fmaxf(fmaxf(red2[4],red2[5]),fmaxf(red2[6],red2[7])));
    float inv = (mx > 0.f) ? 127.f / mx : 0.f;
    if (tid == 0) s_xc[dir][row] = mx * (1.f/127.f);
    #pragma unroll
    for (int j = 0; j < 6; j++) {
        int c = tid + j*256;
        quant2u(vv[j] * inv, &a_xc1[dir][(size_t)row*DI + c], &a_xc2[dir][(size_t)row*DI + c]);
    }
}

// ---------------------------------------------------------------------------
// Split-K reduce for x_proj -> g_dbl f32 + int8 quant of first 48 cols
// ---------------------------------------------------------------------------
__global__ __launch_bounds__(128)
void k_xp_reduce() {
    __shared__ float sm[4];
    int m = blockIdx.x, dir = blockIdx.y;
    int n = threadIdx.x, lane = n & 31, wd = n >> 5;
    float v = 0.f;
    if (n < DBLW) {
        const float* p = g_xp_part[dir][0] + (size_t)m*128 + n;
        #pragma unroll
        for (int sl = 0; sl < XP_SLICES; sl++) v += p[(size_t)sl*RWS*128];
        g_dbl[dir][(size_t)m*DBLW + n] = v;
    }
    float mx = (n < DTR) ? fabsf(v) : 0.f;
    #pragma unroll
    for (int o = 16; o; o >>= 1) mx = fmaxf(mx, __shfl_xor_sync(0xffffffffu, mx, o));
    if (lane == 0) sm[wd] = mx;
    __syncthreads();
    mx = fmaxf(fmaxf(sm[0], sm[1]), fmaxf(sm[2], sm[3]));
    float inv = (mx > 0.f) ? 127.f / mx : 0.f;
    if (n == 0) s_db[dir][m] = mx * (1.f/127.f);
    if (n < DTR)
        quant2u(v * inv, &a_db1[dir][(size_t)m*DTR + n], &a_db2[dir][(size_t)m*DTR + n]);
}

// ---------------------------------------------------------------------------
// Selective scan + D-skip + silu(z) gating -> f32 y
// ---------------------------------------------------------------------------
#define SCAN_TD 128
#define TCH 64

__global__ __launch_bounds__(SCAN_TD)
void k_scan(const float* __restrict__ alF, const float* __restrict__ alB,
            const float* __restrict__ dpF, const float* __restrict__ dpB) {
    int dir = blockIdx.z;
    int b = blockIdx.y;
    int d = blockIdx.x * SCAN_TD + threadIdx.x;

    const float* Alog = (dir ? alB : alF) + (size_t)d * DS;
    float Arow[DS];
    bool fastA = true;
    #pragma unroll
    for (int n = 0; n < DS; n++) {
        Arow[n] = -__expf(Alog[n]);
        float tgt = -(float)(n+1);
        fastA = fastA && (fabsf(Arow[n] - tgt) <= 1e-4f * (float)(n+1));
    }
    float Dv = (dir ? dpB : dpF)[d];

    float h[DS];
    #pragma unroll
    for (int n = 0; n < DS; n++) h[n] = 0.f;

    __shared__ float sB[TCH][DS];
    __shared__ float sC[TCH][DS];

    const float* dbl  = g_dbl[dir];
    const float* delt = g_delta[dir];
    const float* xcb  = g_xc[dir];
    const float* xzb  = g_xz[dir];
    float* yb = g_y[dir];

    for (int t0 = 0; t0 < LSEQ; t0 += TCH) {
        for (int i = threadIdx.x; i < TCH*DS; i += SCAN_TD) {
            int tt = i / DS, n = i % DS;
            size_t r = (size_t)(b*LSEQ + t0 + tt);
            sB[tt][n] = dbl[r*DBLW + DTR + n];
            sC[tt][n] = dbl[r*DBLW + DTR + DS + n];
        }
        __syncthreads();
        if (fastA) {
            for (int tt = 0; tt < TCH; tt++) {
                size_t r = (size_t)(b*LSEQ + t0 + tt);
                float dv = delt[r*DI + d];
                float xv = xcb[r*DI + d];
                float du = dv * xv;
                float e1 = __expf(-dv);
                float p = e1;
                float y = 0.f;
                #pragma unroll
                for (int n = 0; n < DS; n++) {
                    h[n] = h[n]*p + du*sB[tt][n];
                    y += h[n]*sC[tt][n];
                    p *= e1;
                }
                float zv = xzb[r*2*DI + DI + d];
                yb[r*DI + d] = (y + xv*Dv) * (zv / (1.f + __expf(-zv)));
            }
        } else {
            for (int tt = 0; tt < TCH; tt++) {
                size_t r = (size_t)(b*LSEQ + t0 + tt);
                float dv = delt[r*DI + d];
                float xv = xcb[r*DI + d];
                float du = dv * xv;
                float y = 0.f;
                #pragma unroll
                for (int n = 0; n < DS; n++) {
                    float e = __expf(dv * Arow[n]);
                    h[n] = h[n]*e + du*sB[tt][n];
                    y += h[n]*sC[tt][n];
                }
                float zv = xzb[r*2*DI + DI + d];
                yb[r*DI + d] = (y + xv*Dv) * (zv / (1.f + __expf(-zv)));
            }
        }
        __syncthreads();
    }
}

// ---------------------------------------------------------------------------
// Row quant for y -> int8 2-digit
// ---------------------------------------------------------------------------
__global__ __launch_bounds__(256)
void k_rowquant_y() {
    __shared__ float red2[8];
    int row = blockIdx.x, dir = blockIdx.y;
    int tid = threadIdx.x, lane = tid & 31, wid = tid >> 5;
    const float* src = g_y[dir] + (size_t)row * DI;
    float vv[6];
    float mx = 0.f;
    #pragma unroll
    for (int j = 0; j < 6; j++) {
        float v = src[tid + j*256];
        vv[j] = v;
        mx = fmaxf(mx, fabsf(v));
    }
    #pragma unroll
    for (int o = 16; o; o >>= 1) mx = fmaxf(mx, __shfl_xor_sync(0xffffffffu, mx, o));
    if (lane == 0) red2[wid] = mx;
    __syncthreads();
    mx = fmaxf(fmaxf(fmaxf(red2[0],red2[1]),fmaxf(red2[2],red2[3])),
               fmaxf(fmaxf(red2[4],red2[5]),fmaxf(red2[6],red2[7])));
    float inv = (mx > 0.f) ? 127.f / mx : 0.f;
    if (tid == 0) s_y[dir][row] = mx * (1.f/127.f);
    #pragma unroll
    for (int j = 0; j < 6; j++) {
        int c = tid + j*256;
        quant2u(vv[j] * inv, &a_y1[dir][(size_t)row*DI + c], &a_y2[dir][(size_t)row*DI + c]);
    }
}

// ---------------------------------------------------------------------------
// Host launcher
// ---------------------------------------------------------------------------
extern "C" void kernel_launch(void* const* d_in, const int* in_sizes, int n_in,
                              void* d_out, int out_size) {
    (void)in_sizes; (void)n_in; (void)out_size;
    const int* ids = (const int*)d_in[0];
    const float* F[11]; const float* Bw[11];
    for (int i = 0; i < 11; i++) {
        F[i]  = (const float*)d_in[1 + i];
        Bw[i] = (const float*)d_in[12 + i];
    }
    float* out = (float*)d_out;

    static int smem_set = 0;
    if (!smem_set) {
        cudaFuncSetAttribute(k_gemm, cudaFuncAttributeMaxDynamicSharedMemorySize, GEMM_SMEM);
        smem_set = 1;
    }

    // symbol bases
    void* p;
    int8_t *ip1, *ip2, *op1, *op2, *xp1, *xp2, *dt1, *dt2;
    float *swip, *swop, *swxp, *swdt, *xp_part;
    cudaGetSymbolAddress(&p, w_ip1); ip1 = (int8_t*)p;
    cudaGetSymbolAddress(&p, w_ip2); ip2 = (int8_t*)p;
    cudaGetSymbolAddress(&p, w_op1); op1 = (int8_t*)p;
    cudaGetSymbolAddress(&p, w_op2); op2 = (int8_t*)p;
    cudaGetSymbolAddress(&p, w_xp1); xp1 = (int8_t*)p;
    cudaGetSymbolAddress(&p, w_xp2); xp2 = (int8_t*)p;
    cudaGetSymbolAddress(&p, w_dt1); dt1 = (int8_t*)p;
    cudaGetSymbolAddress(&p, w_dt2); dt2 = (int8_t*)p;
    cudaGetSymbolAddress(&p, s_wip); swip = (float*)p;
    cudaGetSymbolAddress(&p, s_wop); swop = (float*)p;
    cudaGetSymbolAddress(&p, s_wxp); swxp = (float*)p;
    cudaGetSymbolAddress(&p, s_wdt); swdt = (float*)p;
    cudaGetSymbolAddress(&p, g_xp_part); xp_part = (float*)p;

    const size_t IPW = (size_t)NL*2*DI*DM, OPW = (size_t)NL*DM*DI;
    const size_t XPW = (size_t)NL*DBLW*DI, DTW = (size_t)NL*DI*DTR;
    const size_t IPS = (size_t)NL*2*DI, OPS = (size_t)NL*DM;
    const size_t XPS = (size_t)NL*DBLW, DTS = (size_t)NL*DI;

    // 1: embedding
    k_embed<<<dim3(RWS, 2), 192>>>(ids, F[0], Bw[0]);
    // 2: in_proj weight quant
    k_wquant<<<dim3(NL*2*DI, 2), 128>>>(F[2], Bw[2], ip1, ip2, swip,
                                        ip1+IPW, ip2+IPW, swip+IPS, DM);

    for (int layer = 0; layer < NL; layer++) {
        const float* nwF = F[1]  + (size_t)layer*DM;
        const float* nwB = Bw[1] + (size_t)layer*DM;
        const float* cwF = F[3]  + (size_t)layer*DI*DC;
        const float* cwB = Bw[3] + (size_t)layer*DI*DC;
        const float* cbF = F[4]  + (size_t)layer*DI;
        const float* cbB = Bw[4] + (size_t)layer*DI;
        const float* dbF = F[7]  + (size_t)layer*DI;
        const float* dbB = Bw[7] + (size_t)layer*DI;
        const float* alF = F[8]  + (size_t)layer*DI*DS;
        const float* alB = Bw[8] + (size_t)layer*DI*DS;
        const float* dpF = F[9]  + (size_t)layer*DI;
        const float* dpB = Bw[9] + (size_t)layer*DI;

        size_t oipw = (size_t)layer*2*DI*DM, oips = (size_t)layer*2*DI;
        size_t oxpw = (size_t)layer*DBLW*DI, oxps = (size_t)layer*DBLW;
        size_t odtw = (size_t)layer*DI*DTR,  odts = (size_t)layer*DI;
        size_t oopw = (size_t)layer*DM*DI,   oops = (size_t)layer*DM;

        // 3 (L0): rmsnorm
        k_rmsnorm<<<dim3(RWS, 2), 256>>>(nwF, nwB);

        // 4 (L0): in_proj GEMM  [2048x768]@[3072x768]^T -> g_xz
        k_gemm<<<dim3(2*DI/128, RWS/128, 2), 512, GEMM_SMEM>>>(
            0, DM, ip1+oipw, ip2+oipw, swip+oips, ip1+IPW+oipw, ip2+IPW+oipw, swip+IPS+oips,
            1, nullptr, RWS, 2*DI, DM, nullptr, nullptr, 0, 0, nullptr);

        if (layer == 0) {
            k_wquant<<<dim3(NL*DBLW, 2), 128>>>(F[5], Bw[5], xp1, xp2, swxp,
                                                xp1+XPW, xp2+XPW, swxp+XPS, DI);
            k_wquant<<<dim3(NL*DI, 2), 128>>>(F[6], Bw[6], dt1, dt2, swdt,
                                              dt1+DTW, dt2+DTW, swdt+DTS, DTR);
            k_wquant<<<dim3(NL*DM, 2), 128>>>(F[10], Bw[10], op1, op2, swop,
                                              op1+OPW, op2+OPW, swop+OPS, DI);
        }

        // conv + quant
        k_conv<<<dim3(RWS, 2), 256>>>(cwF, cwB, cbF, cbB);

        // x_proj split-K (8 slices) -> partials (dequantized f32)
        k_gemm<<<dim3(XP_SLICES, RWS/128, 2), 512, GEMM_SMEM>>>(
            1, DI, xp1+oxpw, xp2+oxpw, swxp+oxps, xp1+XPW+oxpw, xp2+XPW+oxpw, swxp+XPS+oxps,
            0, nullptr, RWS, DBLW, DI, nullptr, nullptr, 0, 1, xp_part);
        k_xp_reduce<<<dim3(RWS, 2), 128>>>();

        // delta GEMM [2048x48]@[1536x48]^T + softplus
        k_gemm<<<dim3(DI/128, RWS/128, 2), 512, GEMM_SMEM>>>(
            2, DTR, dt1+odtw, dt2+odtw, swdt+odts, dt1+DTW+odtw, dt2+DTW+odtw, swdt+DTS+odts,
            4, nullptr, RWS, DI, DTR, dbF, dbB, 1, 0, nullptr);

        // scan -> f32 y, then quant
        k_scan<<<dim3(DI/SCAN_TD, BSZ, 2), SCAN_TD>>>(alF, alB, dpF, dpB);
        k_rowquant_y<<<dim3(RWS, 2), 256>>>();

        // out_proj GEMM -> g_x + fused d_out slice
        k_gemm<<<dim3(DM/128, RWS/128, 2), 512, GEMM_SMEM>>>(
            3, DI, op1+oopw, op2+oopw, swop+oops, op1+OPW+oopw, op2+OPW+oopw, swop+OPS+oops,
            6, out + (size_t)layer*RWS*2*DM, RWS, DM, DI, nullptr, nullptr, 0, 0, nullptr);
    }
}

// round 8
// speedup vs baseline: 1.1671x; 1.1671x over previous
#include <cuda_runtime.h>
#include <cuda_bf16.h>
#include <cstdint>

#define BSZ 2
#define LSEQ 1024
#define DM 768
#define DI 1536
#define DS 16
#define DC 4
#define DTR 48
#define NL 24
#define RWS (BSZ*LSEQ)
#define DBLW (DTR + 2*DS)       /* 80 */
#define EPSF 1e-5f
#define XP_SLICES 8
#define XP_KLEN (DI/XP_SLICES)  /* 192 */
#define OP_SLICES 2
#define OP_KLEN (DI/OP_SLICES)  /* 768 */

typedef __nv_bfloat16 bf16;
typedef __nv_bfloat162 bf162;

// ---------------------------------------------------------------------------
// Scratch
// ---------------------------------------------------------------------------
__device__ float g_x[2][RWS*DM];
__device__ float g_xz[2][RWS*2*DI];
__device__ float g_xc[2][RWS*DI];
__device__ float g_dbl[2][RWS*DBLW];
__device__ float g_delta[2][RWS*DI];
__device__ float g_y[2][RWS*DI];
__device__ float g_xp_part[2][XP_SLICES][RWS*128];
__device__ float g_op_part[2][OP_SLICES][RWS*DM];

__device__ bf16 g_h_hi[2][RWS*DM],   g_h_lo[2][RWS*DM];
__device__ bf16 g_xc_hi[2][RWS*DI],  g_xc_lo[2][RWS*DI];
__device__ bf16 g_dbl_hi[2][RWS*DBLW], g_dbl_lo[2][RWS*DBLW];
__device__ bf16 g_y_hi[2][RWS*DI],   g_y_lo[2][RWS*DI];

__device__ bf16 g_wip_hi[2][NL*2*DI*DM], g_wip_lo[2][NL*2*DI*DM];
__device__ bf16 g_wxp_hi[2][NL*DBLW*DI], g_wxp_lo[2][NL*DBLW*DI];
__device__ bf16 g_wdt_hi[2][NL*DI*DTR],  g_wdt_lo[2][NL*DI*DTR];
__device__ bf16 g_wop_hi[2][NL*DM*DI],   g_wop_lo[2][NL*DM*DI];

__device__ __forceinline__ uint32_t smem_u32(const void* p) {
    uint32_t a;
    asm("{ .reg .u64 t; cvta.to.shared.u64 t, %1; cvt.u32.u64 %0, t; }" : "=r"(a) : "l"(p));
    return a;
}

__device__ __forceinline__ void fsplit(float v, bf16* hp, bf16* lp) {
    bf16 h = __float2bfloat16_rn(v);
    *hp = h;
    *lp = __float2bfloat16_rn(v - __bfloat162float(h));
}

#define CP16(dst, src, sz) \
    asm volatile("cp.async.cg.shared.global [%0], [%1], 16, %2;" \
        :: "r"(dst), "l"(src), "r"(sz) : "memory")
#define CP_COMMIT() asm volatile("cp.async.commit_group;" ::: "memory")
#define CP_WAIT1()  asm volatile("cp.async.wait_group 1;" ::: "memory")
#define CP_WAIT0()  asm volatile("cp.async.wait_group 0;" ::: "memory")

#define LDSM4(r, addr) \
    asm volatile("ldmatrix.sync.aligned.m8n8.x4.shared.b16 {%0,%1,%2,%3}, [%4];" \
        : "=r"((r)[0]), "=r"((r)[1]), "=r"((r)[2]), "=r"((r)[3]) : "r"(addr))

#define MMA16816(c, a, b0v, b1v) \
    asm volatile("mma.sync.aligned.m16n8k16.row.col.f32.bf16.bf16.f32 " \
        "{%0,%1,%2,%3}, {%4,%5,%6,%7}, {%8,%9}, {%0,%1,%2,%3};" \
        : "+f"((c)[0]), "+f"((c)[1]), "+f"((c)[2]), "+f"((c)[3]) \
        : "r"((a)[0]), "r"((a)[1]), "r"((a)[2]), "r"((a)[3]), "r"(b0v), "r"(b1v))

// ---------------------------------------------------------------------------
// Weight split kernels (f32 -> bf16 hi/lo)
// ---------------------------------------------------------------------------
__global__ void k_wsplit(const float4* __restrict__ sF, const float4* __restrict__ sB,
                         bf162* __restrict__ hF, bf162* __restrict__ lF,
                         bf162* __restrict__ hB, bf162* __restrict__ lB, int n4) {
    int i = blockIdx.x * blockDim.x + threadIdx.x;
    if (i >= n4) return;
    const float4* src = blockIdx.y ? sB : sF;
    bf162* hi = blockIdx.y ? hB : hF;
    bf162* lo = blockIdx.y ? lB : lF;
    float4 v = src[i];
    bf162 h01 = __floats2bfloat162_rn(v.x, v.y);
    bf162 h23 = __floats2bfloat162_rn(v.z, v.w);
    bf162 l01 = __floats2bfloat162_rn(v.x - __bfloat162float(h01.x),
                                      v.y - __bfloat162float(h01.y));
    bf162 l23 = __floats2bfloat162_rn(v.z - __bfloat162float(h23.x),
                                      v.w - __bfloat162float(h23.y));
    hi[i*2] = h01; hi[i*2+1] = h23;
    lo[i*2] = l01; lo[i*2+1] = l23;
}

__global__ void k_wsplit2(const float4* __restrict__ s0F, const float4* __restrict__ s0B,
                          bf162* __restrict__ h0F, bf162* __restrict__ l0F,
                          bf162* __restrict__ h0B, bf162* __restrict__ l0B, int n40,
                          const float4* __restrict__ s1F, const float4* __restrict__ s1B,
                          bf162* __restrict__ h1F, bf162* __restrict__ l1F,
                          bf162* __restrict__ h1B, bf162* __restrict__ l1B, int n41) {
    int i = blockIdx.x * blockDim.x + threadIdx.x;
    int set = blockIdx.y >> 1, dir = blockIdx.y & 1;
    const float4* src; bf162 *hi, *lo; int n4;
    if (set == 0) { src = dir ? s0B : s0F; hi = dir ? h0B : h0F; lo = dir ? l0B : l0F; n4 = n40; }
    else          { src = dir ? s1B : s1F; hi = dir ? h1B : h1F; lo = dir ? l1B : l1F; n4 = n41; }
    if (i >= n4) return;
    float4 v = src[i];
    bf162 h01 = __floats2bfloat162_rn(v.x, v.y);
    bf162 h23 = __floats2bfloat162_rn(v.z, v.w);
    bf162 l01 = __floats2bfloat162_rn(v.x - __bfloat162float(h01.x),
                                      v.y - __bfloat162float(h01.y));
    bf162 l23 = __floats2bfloat162_rn(v.z - __bfloat162float(h23.x),
                                      v.w - __bfloat162float(h23.y));
    hi[i*2] = h01; hi[i*2+1] = h23;
    lo[i*2] = l01; lo[i*2+1] = l23;
}

// ---------------------------------------------------------------------------
// Embedding
// ---------------------------------------------------------------------------
__global__ void k_embed(const int* __restrict__ ids,
                        const float* __restrict__ embF,
                        const float* __restrict__ embB) {
    int row = blockIdx.x, dir = blockIdx.y;
    int b = row / LSEQ, l = row % LSEQ;
    int tok = (dir == 0) ? ids[b*LSEQ + l] : ids[b*LSEQ + (LSEQ-1-l)];
    const float* emb = (dir == 0) ? embF : embB;
    const float4* src = (const float4*)(emb + (size_t)tok * DM);
    float4* dst = (float4*)(g_x[dir] + (size_t)row * DM);
    for (int i = threadIdx.x; i < DM/4; i += blockDim.x) dst[i] = src[i];
}

// ---------------------------------------------------------------------------
// RMSNorm -> bf16 hi/lo
// ---------------------------------------------------------------------------
__global__ void k_rmsnorm(const float* __restrict__ wF, const float* __restrict__ wB) {
    int row = blockIdx.x, dir = blockIdx.y;
    const float* x = g_x[dir] + (size_t)row * DM;
    bf16* hh = g_h_hi[dir] + (size_t)row * DM;
    bf16* hl = g_h_lo[dir] + (size_t)row * DM;
    const float* w = dir ? wB : wF;
    float s = 0.f;
    for (int i = threadIdx.x; i < DM; i += 256) { float v = x[i]; s += v*v; }
    #pragma unroll
    for (int o = 16; o; o >>= 1) s += __shfl_down_sync(0xffffffffu, s, o);
    __shared__ float red[8];
    if ((threadIdx.x & 31) == 0) red[threadIdx.x >> 5] = s;
    __syncthreads();
    if (threadIdx.x < 8) {
        float t = red[threadIdx.x];
        #pragma unroll
        for (int o = 4; o; o >>= 1) t += __shfl_down_sync(0xffu, t, o);
        if (threadIdx.x == 0) red[0] = t;
    }
    __syncthreads();
    float inv = rsqrtf(red[0] / (float)DM + EPSF);
    for (int i = threadIdx.x; i < DM; i += 256) {
        float v = x[i] * inv * w[i];
        fsplit(v, hh + i, hl + i);
    }
}

// ---------------------------------------------------------------------------
// Split-bf16 HMMA GEMM.  CTA tile 128(M) x 64(N), 256 threads, 8 warps
// (4M x 2N), warp tile 32x32, K chunks of 64, cp.async double-buffered,
// __launch_bounds__(256,2) -> 2 CTAs/SM.  Optional generalized split-K.
// Stage = AHI(16K)|ALO(16K)|BHI(8K)|BLO(8K) = 48KB.
// ---------------------------------------------------------------------------
#define GTK 64
#define STAGE_B 49152
#define GEMM_SMEM (2*STAGE_B)

__device__ __forceinline__ void stage_tiles(
    uint32_t stg,
    const bf16* __restrict__ Ahi, const bf16* __restrict__ Alo,
    const bf16* __restrict__ Whi, const bf16* __restrict__ Wlo,
    int m0, int n0, int k0, int lda, int ldw, int N, int K, int tid)
{
    #pragma unroll
    for (int t = 0; t < 4; t++) {
        int idx = tid + t*256;            // [0,1024): A 128 rows x 8 cols
        int row = idx >> 3, col = idx & 7;
        int kk = k0 + col*8;
        uint32_t soff = (uint32_t)(row*128 + ((col*16) ^ ((row & 7) << 4)));
        int v = (kk < K) ? 16 : 0;
        size_t go = (size_t)(m0+row)*lda + (v ? kk : 0);
        CP16(stg + soff,         Ahi + go, v);
        CP16(stg + 16384 + soff, Alo + go, v);
    }
    #pragma unroll
    for (int t = 0; t < 2; t++) {
        int idx = tid + t*256;            // [0,512): B 64 rows x 8 cols
        int row = idx >> 3, col = idx & 7;
        int kk = k0 + col*8;
        uint32_t soff = (uint32_t)(row*128 + ((col*16) ^ ((row & 7) << 4)));
        int gn = n0 + row;
        int v = (gn < N && kk < K) ? 16 : 0;
        size_t go = (size_t)(v ? gn : 0)*ldw + (v ? kk : 0);
        CP16(stg + 32768 + soff, Whi + go, v);
        CP16(stg + 40960 + soff, Wlo + go, v);
    }
}

__global__ __launch_bounds__(256, 2)
void k_gemm(int aId, int lda,
            const bf16* __restrict__ Whi0, const bf16* __restrict__ Wlo0,
            const bf16* __restrict__ Whi1, const bf16* __restrict__ Wlo1,
            int cfId, float* __restrict__ outp,
            int M, int N, int K,
            const float* __restrict__ b0, const float* __restrict__ b1,
            int epi, int nsl, int kSlice, int PN, float* __restrict__ partial)
{
    extern __shared__ __align__(1024) char smem[];
    const int dir = blockIdx.z;
    const bf16 *Ahi, *Alo;
    switch (aId) {
        case 0: Ahi = g_h_hi[dir];   Alo = g_h_lo[dir];   break;
        case 1: Ahi = g_xc_hi[dir];  Alo = g_xc_lo[dir];  break;
        case 2: Ahi = g_dbl_hi[dir]; Alo = g_dbl_lo[dir]; break;
        default: Ahi = g_y_hi[dir];  Alo = g_y_lo[dir];   break;
    }
    const bf16* Whi = dir ? Whi1 : Whi0;
    const bf16* Wlo = dir ? Wlo1 : Wlo0;
    const float* bias = dir ? b1 : b0;

    const uint32_t tb = smem_u32(smem);
    const int tid = threadIdx.x, lane = tid & 31, wid = tid >> 5;
    const int wm = wid & 3, wn = wid >> 2;     // 4 x 2 warp grid
    const int m0 = blockIdx.y * 128;
    int n0, kbase, kLen, slice = 0;
    if (nsl > 1) {
        int ntN = (N + 63) >> 6;
        slice = blockIdx.x / ntN;
        n0 = (blockIdx.x - slice * ntN) * 64;
        kbase = slice * kSlice;
        kLen = kSlice;
    } else {
        n0 = blockIdx.x * 64; kbase = 0; kLen = K;
    }

    const int l15 = lane & 15;
    const int a_kbx = (lane & 16) ? 16 : 0;
    const int b_nrow = (lane & 7) + ((lane & 16) ? 8 : 0);
    const int b_kbx = (lane & 8) ? 16 : 0;

    uint32_t aOff[2], aMsk[2];
    #pragma unroll
    for (int mt = 0; mt < 2; mt++) {
        int r = wm*32 + mt*16 + l15;
        aOff[mt] = r * 128;
        aMsk[mt] = (r & 7) << 4;
    }
    uint32_t bOff[2], bMsk[2];
    #pragma unroll
    for (int g = 0; g < 2; g++) {
        int r = wn*32 + g*16 + b_nrow;
        bOff[g] = r * 128;
        bMsk[g] = (r & 7) << 4;
    }

    float cf[2][4][4];
    #pragma unroll
    for (int i = 0; i < 2; i++)
        #pragma unroll
        for (int j = 0; j < 4; j++)
            #pragma unroll
            for (int q = 0; q < 4; q++) cf[i][j][q] = 0.f;

    const int nch = (kLen + GTK - 1) / GTK;
    stage_tiles(tb, Ahi, Alo, Whi, Wlo, m0, n0, kbase, lda, K, N, K, tid);
    CP_COMMIT();

    for (int ch = 0; ch < nch; ch++) {
        if (ch + 1 < nch) {
            stage_tiles(tb + ((ch+1)&1)*STAGE_B, Ahi, Alo, Whi, Wlo,
                        m0, n0, kbase + (ch+1)*GTK, lda, K, N, K, tid);
            CP_COMMIT();
            CP_WAIT1();
        } else {
            CP_WAIT0();
        }
        __syncthreads();

        const uint32_t AHI = tb + (ch&1)*STAGE_B;
        const uint32_t ALO = AHI + 16384, BHI = AHI + 32768, BLO = AHI + 40960;
        #pragma unroll
        for (int ks = 0; ks < 4; ks++) {
            const int kb = ks * 32;
            uint32_t ah[2][4], al[2][4], bh[2][4], bl[2][4];
            #pragma unroll
            for (int mt = 0; mt < 2; mt++) {
                uint32_t kx = (uint32_t)(kb + a_kbx) ^ aMsk[mt];
                LDSM4(ah[mt], AHI + aOff[mt] + kx);
                LDSM4(al[mt], ALO + aOff[mt] + kx);
            }
            #pragma unroll
            for (int g = 0; g < 2; g++) {
                uint32_t kx = (uint32_t)(kb + b_kbx) ^ bMsk[g];
                LDSM4(bh[g], BHI + bOff[g] + kx);
                LDSM4(bl[g], BLO + bOff[g] + kx);
            }
            #pragma unroll
            for (int mt = 0; mt < 2; mt++)
                #pragma unroll
                for (int nt = 0; nt < 4; nt++) {
                    int g = nt >> 1, o = (nt & 1) * 2;
                    float* cc = cf[mt][nt];
                    MMA16816(cc, ah[mt], bh[g][o], bh[g][o+1]);
                    MMA16816(cc, ah[mt], bl[g][o], bl[g][o+1]);
                    MMA16816(cc, al[mt], bh[g][o], bh[g][o+1]);
                }
        }
        __syncthreads();
    }

    // ---- epilogue ----
    const int mrow = m0 + wm*32 + (lane >> 2);
    const int ncl = wn*32 + (lane & 3)*2;
    if (partial) {
        float* pbase = partial + ((size_t)(dir*nsl + slice)) * (size_t)M * PN;
        #pragma unroll
        for (int mt = 0; mt < 2; mt++)
            #pragma unroll
            for (int nt = 0; nt < 4; nt++) {
                int n = n0 + ncl + nt*8;
                if (n >= PN) continue;
                #pragma unroll
                for (int half = 0; half < 2; half++) {
                    int m = mrow + mt*16 + half*8;
                    *(float2*)(pbase + (size_t)m*PN + n) =
                        make_float2(cf[mt][nt][half*2], cf[mt][nt][half*2+1]);
                }
            }
        return;
    }
    float* Cf = (cfId == 1) ? g_xz[dir] : ((cfId == 4) ? g_delta[dir] : g_x[dir]);
    #pragma unroll
    for (int mt = 0; mt < 2; mt++) {
        #pragma unroll
        for (int nt = 0; nt < 4; nt++) {
            int n = n0 + ncl + nt*8;
            if (n >= N) continue;
            #pragma unroll
            for (int half = 0; half < 2; half++) {
                int m = mrow + mt*16 + half*8;
                float v0 = cf[mt][nt][half*2+0];
                float v1 = cf[mt][nt][half*2+1];
                if (epi == 1) {
                    v0 += bias[n];   v1 += bias[n+1];
                    v0 = (v0 > 20.f) ? v0 : log1pf(__expf(v0));
                    v1 = (v1 > 20.f) ? v1 : log1pf(__expf(v1));
                }
                *(float2*)(Cf + (size_t)m*N + n) = make_float2(v0, v1);
                if (outp)
                    *(float2*)(outp + (size_t)m*(2*DM) + dir*DM + n) = make_float2(v0, v1);
            }
        }
    }
}

// ---------------------------------------------------------------------------
// out_proj split-K reduce -> g_x + d_out slice
// ---------------------------------------------------------------------------
__global__ __launch_bounds__(256)
void k_op_reduce(float* __restrict__ outp) {
    int idx = blockIdx.x * 256 + threadIdx.x;   // over RWS*DM/4
    int dir = blockIdx.y;
    if (idx >= RWS*DM/4) return;
    float4 a = ((const float4*)g_op_part[dir][0])[idx];
    float4 b = ((const float4*)g_op_part[dir][1])[idx];
    float4 v = make_float4(a.x+b.x, a.y+b.y, a.z+b.z, a.w+b.w);
    ((float4*)g_x[dir])[idx] = v;
    int m = idx / (DM/4), c4 = idx % (DM/4);
    *(float4*)(outp + (size_t)m*(2*DM) + dir*DM + c4*4) = v;
}

// ---------------------------------------------------------------------------
// x_proj split-K reduce -> g_dbl f32 + bf16 hi/lo
// ---------------------------------------------------------------------------
__global__ void k_xp_reduce() {
    int idx = blockIdx.x * blockDim.x + threadIdx.x;   // over RWS*DBLW
    int dir = blockIdx.y;
    if (idx >= RWS*DBLW) return;
    int m = idx / DBLW, n = idx % DBLW;
    const float* p = g_xp_part[dir][0] + (size_t)m*128 + n;
    float s = 0.f;
    #pragma unroll
    for (int sl = 0; sl < XP_SLICES; sl++) s += p[(size_t)sl*RWS*128];
    g_dbl[dir][idx] = s;
    fsplit(s, &g_dbl_hi[dir][idx], &g_dbl_lo[dir][idx]);
}

// ---------------------------------------------------------------------------
// Conv1d (k=4) + bias + SiLU -> f32 + bf16 hi/lo
// ---------------------------------------------------------------------------
__global__ void k_conv(const float* __restrict__ cwF, const float* __restrict__ cwB,
                       const float* __restrict__ cbF, const float* __restrict__ cbB) {
    int idx = blockIdx.x * blockDim.x + threadIdx.x;
    int dir = blockIdx.y;
    if (idx >= RWS*DI) return;
    int row = idx / DI, c = idx % DI;
    int b = row / LSEQ, l = row % LSEQ;
    const float* cw = (dir ? cwB : cwF) + c*DC;
    float acc = (dir ? cbB : cbF)[c];
    const float* xz = g_xz[dir];
    #pragma unroll
    for (int k = 0; k < DC; k++) {
        int ls = l - (DC-1) + k;
        if (ls >= 0) acc += xz[((size_t)(b*LSEQ + ls))*2*DI + c] * cw[k];
    }
    float v = acc / (1.f + __expf(-acc));
    g_xc[dir][idx] = v;
    fsplit(v, &g_xc_hi[dir][idx], &g_xc_lo[dir][idx]);
}

// ---------------------------------------------------------------------------
// Selective scan + D-skip + silu(z) gating -> bf16 hi/lo y
// ---------------------------------------------------------------------------
#define SCAN_TD 128
#define TCH 64

__global__ __launch_bounds__(SCAN_TD)
void k_scan(const float* __restrict__ alF, const float* __restrict__ alB,
            const float* __restrict__ dpF, const float* __restrict__ dpB) {
    int dir = blockIdx.z;
    int b = blockIdx.y;
    int d = blockIdx.x * SCAN_TD + threadIdx.x;

    const float* Alog = (dir ? alB : alF) + (size_t)d * DS;
    float Arow[DS];
    bool fastA = true;
    #pragma unroll
    for (int n = 0; n < DS; n++) {
        Arow[n] = -__expf(Alog[n]);
        float tgt = -(float)(n+1);
        fastA = fastA && (fabsf(Arow[n] - tgt) <= 1e-4f * (float)(n+1));
    }
    float Dv = (dir ? dpB : dpF)[d];

    float h[DS];
    #pragma unroll
    for (int n = 0; n < DS; n++) h[n] = 0.f;

    __shared__ float sB[TCH][DS];
    __shared__ float sC[TCH][DS];

    const float* dbl  = g_dbl[dir];
    const float* delt = g_delta[dir];
    const float* xcb  = g_xc[dir];
    const float* xzb  = g_xz[dir];
    bf16* yh = g_y_hi[dir];
    bf16* yl = g_y_lo[dir];

    for (int t0 = 0; t0 < LSEQ; t0 += TCH) {
        for (int i = threadIdx.x; i < TCH*DS; i += SCAN_TD) {
            int tt = i / DS, n = i % DS;
            size_t r = (size_t)(b*LSEQ + t0 + tt);
            sB[tt][n] = dbl[r*DBLW + DTR + n];
            sC[tt][n] = dbl[r*DBLW + DTR + DS + n];
        }
        __syncthreads();
        if (fastA) {
            for (int tt = 0; tt < TCH; tt++) {
                size_t r = (size_t)(b*LSEQ + t0 + tt);
                float dv = delt[r*DI + d];
                float xv = xcb[r*DI + d];
                float du = dv * xv;
                float e1 = __expf(-dv);
                float p = e1;
                float y = 0.f;
                #pragma unroll
                for (int n = 0; n < DS; n++) {
                    h[n] = h[n]*p + du*sB[tt][n];
                    y += h[n]*sC[tt][n];
                    p *= e1;
                }
                float zv = xzb[r*2*DI + DI + d];
                float yv = (y + xv*Dv) * (zv / (1.f + __expf(-zv)));
                fsplit(yv, yh + r*DI + d, yl + r*DI + d);
            }
        } else {
            for (int tt = 0; tt < TCH; tt++) {
                size_t r = (size_t)(b*LSEQ + t0 + tt);
                float dv = delt[r*DI + d];
                float xv = xcb[r*DI + d];
                float du = dv * xv;
                float y = 0.f;
                #pragma unroll
                for (int n = 0; n < DS; n++) {
                    float e = __expf(dv * Arow[n]);
                    h[n] = h[n]*e + du*sB[tt][n];
                    y += h[n]*sC[tt][n];
                }
                float zv = xzb[r*2*DI + DI + d];
                float yv = (y + xv*Dv) * (zv / (1.f + __expf(-zv)));
                fsplit(yv, yh + r*DI + d, yl + r*DI + d);
            }
        }
        __syncthreads();
    }
}

// ---------------------------------------------------------------------------
// Host launcher
// ---------------------------------------------------------------------------
extern "C" void kernel_launch(void* const* d_in, const int* in_sizes, int n_in,
                              void* d_out, int out_size) {
    (void)in_sizes; (void)n_in; (void)out_size;
    const int* ids = (const int*)d_in[0];
    const float* F[11]; const float* Bw[11];
    for (int i = 0; i < 11; i++) {
        F[i]  = (const float*)d_in[1 + i];
        Bw[i] = (const float*)d_in[12 + i];
    }
    float* out = (float*)d_out;

    static int smem_set = 0;
    if (!smem_set) {
        cudaFuncSetAttribute(k_gemm, cudaFuncAttributeMaxDynamicSharedMemorySize, GEMM_SMEM);
        smem_set = 1;
    }

    bf16 *wip_hi[2], *wip_lo[2], *wxp_hi[2], *wxp_lo[2];
    bf16 *wdt_hi[2], *wdt_lo[2], *wop_hi[2], *wop_lo[2];
    float *xp_part, *op_part;
    {
        void* p;
        cudaGetSymbolAddress(&p, g_wip_hi); wip_hi[0]=(bf16*)p; wip_hi[1]=(bf16*)p + (size_t)NL*2*DI*DM;
        cudaGetSymbolAddress(&p, g_wip_lo); wip_lo[0]=(bf16*)p; wip_lo[1]=(bf16*)p + (size_t)NL*2*DI*DM;
        cudaGetSymbolAddress(&p, g_wxp_hi); wxp_hi[0]=(bf16*)p; wxp_hi[1]=(bf16*)p + (size_t)NL*DBLW*DI;
        cudaGetSymbolAddress(&p, g_wxp_lo); wxp_lo[0]=(bf16*)p; wxp_lo[1]=(bf16*)p + (size_t)NL*DBLW*DI;
        cudaGetSymbolAddress(&p, g_wdt_hi); wdt_hi[0]=(bf16*)p; wdt_hi[1]=(bf16*)p + (size_t)NL*DI*DTR;
        cudaGetSymbolAddress(&p, g_wdt_lo); wdt_lo[0]=(bf16*)p; wdt_lo[1]=(bf16*)p + (size_t)NL*DI*DTR;
        cudaGetSymbolAddress(&p, g_wop_hi); wop_hi[0]=(bf16*)p; wop_hi[1]=(bf16*)p + (size_t)NL*DM*DI;
        cudaGetSymbolAddress(&p, g_wop_lo); wop_lo[0]=(bf16*)p; wop_lo[1]=(bf16*)p + (size_t)NL*DM*DI;
        cudaGetSymbolAddress(&p, g_xp_part); xp_part = (float*)p;
        cudaGetSymbolAddress(&p, g_op_part); op_part = (float*)p;
    }

    // 1: embedding
    k_embed<<<dim3(RWS, 2), 192>>>(ids, F[0], Bw[0]);
    // 2: in_proj weight split
    {
        int n4 = NL*2*DI*DM/4;
        k_wsplit<<<dim3((n4+255)/256, 2), 256>>>(
            (const float4*)F[2], (const float4*)Bw[2],
            (bf162*)wip_hi[0], (bf162*)wip_lo[0], (bf162*)wip_hi[1], (bf162*)wip_lo[1], n4);
    }

    for (int layer = 0; layer < NL; layer++) {
        const float* nwF = F[1]  + (size_t)layer*DM;
        const float* nwB = Bw[1] + (size_t)layer*DM;
        const float* cwF = F[3]  + (size_t)layer*DI*DC;
        const float* cwB = Bw[3] + (size_t)layer*DI*DC;
        const float* cbF = F[4]  + (size_t)layer*DI;
        const float* cbB = Bw[4] + (size_t)layer*DI;
        const float* dbF = F[7]  + (size_t)layer*DI;
        const float* dbB = Bw[7] + (size_t)layer*DI;
        const float* alF = F[8]  + (size_t)layer*DI*DS;
        const float* alB = Bw[8] + (size_t)layer*DI*DS;
        const float* dpF = F[9]  + (size_t)layer*DI;
        const float* dpB = Bw[9] + (size_t)layer*DI;

        size_t oip = (size_t)layer*2*DI*DM;
        size_t oxp = (size_t)layer*DBLW*DI;
        size_t odt = (size_t)layer*DI*DTR;
        size_t oop = (size_t)layer*DM*DI;

        // rmsnorm
        k_rmsnorm<<<dim3(RWS, 2), 256>>>(nwF, nwB);

        // in_proj: [2048x768]@[3072x768]^T -> g_xz   (ncu capture target)
        k_gemm<<<dim3(2*DI/64, RWS/128, 2), 256, GEMM_SMEM>>>(
            0, DM, wip_hi[0]+oip, wip_lo[0]+oip, wip_hi[1]+oip, wip_lo[1]+oip,
            1, nullptr, RWS, 2*DI, DM, nullptr, nullptr, 0, 1, 0, 0, nullptr);

        if (layer == 0) {
            int n4 = NL*DM*DI/4;
            k_wsplit<<<dim3((n4+255)/256, 2), 256>>>(
                (const float4*)F[10], (const float4*)Bw[10],
                (bf162*)wop_hi[0], (bf162*)wop_lo[0], (bf162*)wop_hi[1], (bf162*)wop_lo[1], n4);
            int n40 = NL*DBLW*DI/4, n41 = NL*DI*DTR/4;
            int gx = ((n40 > n41 ? n40 : n41) + 255)/256;
            k_wsplit2<<<dim3(gx, 4), 256>>>(
                (const float4*)F[5], (const float4*)Bw[5],
                (bf162*)wxp_hi[0], (bf162*)wxp_lo[0], (bf162*)wxp_hi[1], (bf162*)wxp_lo[1], n40,
                (const float4*)F[6], (const float4*)Bw[6],
                (bf162*)wdt_hi[0], (bf162*)wdt_lo[0], (bf162*)wdt_hi[1], (bf162*)wdt_lo[1], n41);
        }

        // conv + split
        k_conv<<<dim3(RWS*DI/256, 2), 256>>>(cwF, cwB, cbF, cbB);

        // x_proj split-K=8: grid.x = 8 slices x 2 n-tiles
        k_gemm<<<dim3(XP_SLICES*2, RWS/128, 2), 256, GEMM_SMEM>>>(
            1, DI, wxp_hi[0]+oxp, wxp_lo[0]+oxp, wxp_hi[1]+oxp, wxp_lo[1]+oxp,
            0, nullptr, RWS, DBLW, DI, nullptr, nullptr, 0, XP_SLICES, XP_KLEN, 128, xp_part);
        k_xp_reduce<<<dim3((RWS*DBLW+255)/256, 2), 256>>>();

        // delta: softplus epi
        k_gemm<<<dim3(DI/64, RWS/128, 2), 256, GEMM_SMEM>>>(
            2, DBLW, wdt_hi[0]+odt, wdt_lo[0]+odt, wdt_hi[1]+odt, wdt_lo[1]+odt,
            4, nullptr, RWS, DI, DTR, dbF, dbB, 1, 1, 0, 0, nullptr);

        k_scan<<<dim3(DI/SCAN_TD, BSZ, 2), SCAN_TD>>>(alF, alB, dpF, dpB);

        // out_proj split-K=2: grid.x = 2 slices x 12 n-tiles
        k_gemm<<<dim3(OP_SLICES*(DM/64), RWS/128, 2), 256, GEMM_SMEM>>>(
            3, DI, wop_hi[0]+oop, wop_lo[0]+oop, wop_hi[1]+oop, wop_lo[1]+oop,
            0, nullptr, RWS, DM, DI, nullptr, nullptr, 0, OP_SLICES, OP_KLEN, DM, op_part);
        k_op_reduce<<<dim3((RWS*DM/4+255)/256, 2), 256>>>(out + (size_t)layer*RWS*2*DM);
    }
}

// round 9
// speedup vs baseline: 1.6027x; 1.3733x over previous
#include <cuda_runtime.h>
#include <cuda_bf16.h>
#include <cstdint>

#define BSZ 2
#define LSEQ 1024
#define DM 768
#define DI 1536
#define DS 16
#define DC 4
#define DTR 48
#define NL 24
#define RWS (BSZ*LSEQ)
#define DBLW (DTR + 2*DS)       /* 80 */
#define EPSF 1e-5f
#define XP_SLICES 8
#define XP_KLEN (DI/XP_SLICES)  /* 192 */

typedef __nv_bfloat16 bf16;
typedef __nv_bfloat162 bf162;

// ---------------------------------------------------------------------------
// Scratch
// ---------------------------------------------------------------------------
__device__ float g_x[2][RWS*DM];
__device__ float g_xz[2][RWS*2*DI];
__device__ float g_xc[2][RWS*DI];
__device__ float g_dbl[2][RWS*DBLW];
__device__ float g_delta[2][RWS*DI];
__device__ float g_xp_part[2][XP_SLICES][RWS*128];

__device__ bf16 g_h_hi[2][RWS*DM],   g_h_lo[2][RWS*DM];
__device__ bf16 g_xc_hi[2][RWS*DI],  g_xc_lo[2][RWS*DI];
__device__ bf16 g_dbl_hi[2][RWS*DBLW], g_dbl_lo[2][RWS*DBLW];
__device__ bf16 g_y_hi[2][RWS*DI],   g_y_lo[2][RWS*DI];

__device__ bf16 g_wip_hi[2][NL*2*DI*DM], g_wip_lo[2][NL*2*DI*DM];
__device__ bf16 g_wxp_hi[2][NL*DBLW*DI], g_wxp_lo[2][NL*DBLW*DI];
__device__ bf16 g_wdt_hi[2][NL*DI*DTR],  g_wdt_lo[2][NL*DI*DTR];
__device__ bf16 g_wop_hi[2][NL*DM*DI],   g_wop_lo[2][NL*DM*DI];

__device__ __forceinline__ uint32_t smem_u32(const void* p) {
    uint32_t a;
    asm("{ .reg .u64 t; cvta.to.shared.u64 t, %1; cvt.u32.u64 %0, t; }" : "=r"(a) : "l"(p));
    return a;
}

__device__ __forceinline__ void fsplit(float v, bf16* hp, bf16* lp) {
    bf16 h = __float2bfloat16_rn(v);
    *hp = h;
    *lp = __float2bfloat16_rn(v - __bfloat162float(h));
}

__device__ __forceinline__ const bf16* actA_hi(int aId, int dir) {
    switch (aId) {
        case 0: return g_h_hi[dir];
        case 1: return g_xc_hi[dir];
        case 2: return g_dbl_hi[dir];
        default: return g_y_hi[dir];
    }
}
__device__ __forceinline__ const bf16* actA_lo(int aId, int dir) {
    switch (aId) {
        case 0: return g_h_lo[dir];
        case 1: return g_xc_lo[dir];
        case 2: return g_dbl_lo[dir];
        default: return g_y_lo[dir];
    }
}
__device__ __forceinline__ float* getCf(int cfId, int dir) {
    switch (cfId) {
        case 1: return g_xz[dir];
        case 4: return g_delta[dir];
        default: return g_x[dir];
    }
}

#define CP16(dst, src, sz) \
    asm volatile("cp.async.cg.shared.global [%0], [%1], 16, %2;" \
        :: "r"(dst), "l"(src), "r"(sz) : "memory")
#define CP_COMMIT() asm volatile("cp.async.commit_group;" ::: "memory")
#define CP_WAIT1()  asm volatile("cp.async.wait_group 1;" ::: "memory")
#define CP_WAIT0()  asm volatile("cp.async.wait_group 0;" ::: "memory")

#define LDSM4(r, addr) \
    asm volatile("ldmatrix.sync.aligned.m8n8.x4.shared.b16 {%0,%1,%2,%3}, [%4];" \
        : "=r"((r)[0]), "=r"((r)[1]), "=r"((r)[2]), "=r"((r)[3]) : "r"(addr))

#define MMA16816(c, a, b0v, b1v) \
    asm volatile("mma.sync.aligned.m16n8k16.row.col.f32.bf16.bf16.f32 " \
        "{%0,%1,%2,%3}, {%4,%5,%6,%7}, {%8,%9}, {%0,%1,%2,%3};" \
        : "+f"((c)[0]), "+f"((c)[1]), "+f"((c)[2]), "+f"((c)[3]) \
        : "r"((a)[0]), "r"((a)[1]), "r"((a)[2]), "r"((a)[3]), "r"(b0v), "r"(b1v))

// ---------------------------------------------------------------------------
// Weight split kernels (f32 -> bf16 hi/lo)
// ---------------------------------------------------------------------------
__global__ void k_wsplit(const float4* __restrict__ sF, const float4* __restrict__ sB,
                         bf162* __restrict__ hF, bf162* __restrict__ lF,
                         bf162* __restrict__ hB, bf162* __restrict__ lB, int n4) {
    int i = blockIdx.x * blockDim.x + threadIdx.x;
    if (i >= n4) return;
    const float4* src = blockIdx.y ? sB : sF;
    bf162* hi = blockIdx.y ? hB : hF;
    bf162* lo = blockIdx.y ? lB : lF;
    float4 v = src[i];
    bf162 h01 = __floats2bfloat162_rn(v.x, v.y);
    bf162 h23 = __floats2bfloat162_rn(v.z, v.w);
    bf162 l01 = __floats2bfloat162_rn(v.x - __bfloat162float(h01.x),
                                      v.y - __bfloat162float(h01.y));
    bf162 l23 = __floats2bfloat162_rn(v.z - __bfloat162float(h23.x),
                                      v.w - __bfloat162float(h23.y));
    hi[i*2] = h01; hi[i*2+1] = h23;
    lo[i*2] = l01; lo[i*2+1] = l23;
}

__global__ void k_wsplit2(const float4* __restrict__ s0F, const float4* __restrict__ s0B,
                          bf162* __restrict__ h0F, bf162* __restrict__ l0F,
                          bf162* __restrict__ h0B, bf162* __restrict__ l0B, int n40,
                          const float4* __restrict__ s1F, const float4* __restrict__ s1B,
                          bf162* __restrict__ h1F, bf162* __restrict__ l1F,
                          bf162* __restrict__ h1B, bf162* __restrict__ l1B, int n41) {
    int i = blockIdx.x * blockDim.x + threadIdx.x;
    int set = blockIdx.y >> 1, dir = blockIdx.y & 1;
    const float4* src; bf162 *hi, *lo; int n4;
    if (set == 0) { src = dir ? s0B : s0F; hi = dir ? h0B : h0F; lo = dir ? l0B : l0F; n4 = n40; }
    else          { src = dir ? s1B : s1F; hi = dir ? h1B : h1F; lo = dir ? l1B : l1F; n4 = n41; }
    if (i >= n4) return;
    float4 v = src[i];
    bf162 h01 = __floats2bfloat162_rn(v.x, v.y);
    bf162 h23 = __floats2bfloat162_rn(v.z, v.w);
    bf162 l01 = __floats2bfloat162_rn(v.x - __bfloat162float(h01.x),
                                      v.y - __bfloat162float(h01.y));
    bf162 l23 = __floats2bfloat162_rn(v.z - __bfloat162float(h23.x),
                                      v.w - __bfloat162float(h23.y));
    hi[i*2] = h01; hi[i*2+1] = h23;
    lo[i*2] = l01; lo[i*2+1] = l23;
}

// ---------------------------------------------------------------------------
// Embedding
// ---------------------------------------------------------------------------
__global__ void k_embed(const int* __restrict__ ids,
                        const float* __restrict__ embF,
                        const float* __restrict__ embB) {
    int row = blockIdx.x, dir = blockIdx.y;
    int b = row / LSEQ, l = row % LSEQ;
    int tok = (dir == 0) ? ids[b*LSEQ + l] : ids[b*LSEQ + (LSEQ-1-l)];
    const float* emb = (dir == 0) ? embF : embB;
    const float4* src = (const float4*)(emb + (size_t)tok * DM);
    float4* dst = (float4*)(g_x[dir] + (size_t)row * DM);
    for (int i = threadIdx.x; i < DM/4; i += blockDim.x) dst[i] = src[i];
}

// ---------------------------------------------------------------------------
// RMSNorm -> bf16 hi/lo
// ---------------------------------------------------------------------------
__global__ void k_rmsnorm(const float* __restrict__ wF, const float* __restrict__ wB) {
    int row = blockIdx.x, dir = blockIdx.y;
    const float* x = g_x[dir] + (size_t)row * DM;
    bf16* hh = g_h_hi[dir] + (size_t)row * DM;
    bf16* hl = g_h_lo[dir] + (size_t)row * DM;
    const float* w = dir ? wB : wF;
    float s = 0.f;
    for (int i = threadIdx.x; i < DM; i += 256) { float v = x[i]; s += v*v; }
    #pragma unroll
    for (int o = 16; o; o >>= 1) s += __shfl_down_sync(0xffffffffu, s, o);
    __shared__ float red[8];
    if ((threadIdx.x & 31) == 0) red[threadIdx.x >> 5] = s;
    __syncthreads();
    if (threadIdx.x < 8) {
        float t = red[threadIdx.x];
        #pragma unroll
        for (int o = 4; o; o >>= 1) t += __shfl_down_sync(0xffu, t, o);
        if (threadIdx.x == 0) red[0] = t;
    }
    __syncthreads();
    float inv = rsqrtf(red[0] / (float)DM + EPSF);
    for (int i = threadIdx.x; i < DM; i += 256) {
        float v = x[i] * inv * w[i];
        fsplit(v, hh + i, hl + i);
    }
}

// ===========================================================================
// KERNEL A (R6): 128x128 tile, 512 threads (16 warps, 4Mx4N), warp 32x32,
// K chunk 64, cp.async double-buffered, 1 CTA/SM.  Used for x_proj (split-K)
// and delta (softplus epi).
// ===========================================================================
#define GTK 64
#define STAGE512 65536
#define SMEM512 (2*STAGE512)

__device__ __forceinline__ void stage512(
    uint32_t stg,
    const bf16* __restrict__ Ahi, const bf16* __restrict__ Alo,
    const bf16* __restrict__ Whi, const bf16* __restrict__ Wlo,
    int m0, int n0, int k0, int lda, int ldw, int N, int K, int tid)
{
    #pragma unroll
    for (int t = 0; t < 2; t++) {
        int idx = tid + t*512;
        int row = idx >> 3, col = idx & 7;
        int kk = k0 + col*8;
        uint32_t soff = (uint32_t)(row*128 + ((col*16) ^ ((row & 7) << 4)));
        int asz = (kk < K) ? 16 : 0;
        size_t aoffm = (size_t)(m0+row)*lda + (asz ? kk : 0);
        CP16(stg + soff,          Ahi + aoffm, asz);
        CP16(stg + 16384 + soff,  Alo + aoffm, asz);
        int gn = n0 + row;
        int bsz = (gn < N && kk < K) ? 16 : 0;
        size_t boff = (size_t)(bsz ? gn : 0)*ldw + (bsz ? kk : 0);
        CP16(stg + 32768 + soff,  Whi + boff, bsz);
        CP16(stg + 49152 + soff,  Wlo + boff, bsz);
    }
}

__global__ __launch_bounds__(512, 1)
void k_gemm512(int aId, int lda,
               const bf16* __restrict__ Whi0, const bf16* __restrict__ Wlo0,
               const bf16* __restrict__ Whi1, const bf16* __restrict__ Wlo1,
               int cfId, int M, int N, int K,
               const float* __restrict__ b0, const float* __restrict__ b1,
               int epi, int splitK, float* __restrict__ partial)
{
    extern __shared__ __align__(1024) char smem[];
    const int dir = blockIdx.z;
    const bf16* Ahi = actA_hi(aId, dir);
    const bf16* Alo = actA_lo(aId, dir);
    const bf16* Whi = dir ? Whi1 : Whi0;
    const bf16* Wlo = dir ? Wlo1 : Wlo0;
    const float* bias = dir ? b1 : b0;

    const uint32_t tb = smem_u32(smem);
    const int tid = threadIdx.x, lane = tid & 31, wid = tid >> 5;
    const int wm = wid & 3, wn = wid >> 2;
    const int m0 = blockIdx.y * 128;
    int n0, kbase, kLen, slice = 0;
    if (splitK) { slice = blockIdx.x; n0 = 0; kLen = XP_KLEN; kbase = slice * XP_KLEN; }
    else        { n0 = blockIdx.x * 128; kLen = K; kbase = 0; }

    const int l15 = lane & 15;
    const int a_kbx = (lane & 16) ? 16 : 0;
    const int b_nrow = (lane & 7) + ((lane & 16) ? 8 : 0);
    const int b_kbx = (lane & 8) ? 16 : 0;

    uint32_t aOff[2], aMsk[2];
    #pragma unroll
    for (int mt = 0; mt < 2; mt++) {
        int r = wm*32 + mt*16 + l15;
        aOff[mt] = r * 128;
        aMsk[mt] = (r & 7) << 4;
    }
    uint32_t bOff[2], bMsk[2];
    #pragma unroll
    for (int g = 0; g < 2; g++) {
        int r = wn*32 + g*16 + b_nrow;
        bOff[g] = r * 128;
        bMsk[g] = (r & 7) << 4;
    }

    float cf[2][4][4];
    #pragma unroll
    for (int i = 0; i < 2; i++)
        #pragma unroll
        for (int j = 0; j < 4; j++)
            #pragma unroll
            for (int q = 0; q < 4; q++) cf[i][j][q] = 0.f;

    const int nch = (kLen + GTK - 1) / GTK;
    stage512(tb, Ahi, Alo, Whi, Wlo, m0, n0, kbase, lda, K, N, K, tid);
    CP_COMMIT();

    for (int ch = 0; ch < nch; ch++) {
        if (ch + 1 < nch) {
            stage512(tb + ((ch+1)&1)*STAGE512, Ahi, Alo, Whi, Wlo,
                     m0, n0, kbase + (ch+1)*GTK, lda, K, N, K, tid);
            CP_COMMIT();
            CP_WAIT1();
        } else {
            CP_WAIT0();
        }
        __syncthreads();

        const uint32_t AHI = tb + (ch&1)*STAGE512;
        const uint32_t ALO = AHI + 16384, BHI = AHI + 32768, BLO = AHI + 49152;
        #pragma unroll
        for (int ks = 0; ks < 4; ks++) {
            const int kb = ks * 32;
            uint32_t ah[2][4], al[2][4], bh[2][4], bl[2][4];
            #pragma unroll
            for (int mt = 0; mt < 2; mt++) {
                uint32_t kx = (uint32_t)(kb + a_kbx) ^ aMsk[mt];
                LDSM4(ah[mt], AHI + aOff[mt] + kx);
                LDSM4(al[mt], ALO + aOff[mt] + kx);
            }
            #pragma unroll
            for (int g = 0; g < 2; g++) {
                uint32_t kx = (uint32_t)(kb + b_kbx) ^ bMsk[g];
                LDSM4(bh[g], BHI + bOff[g] + kx);
                LDSM4(bl[g], BLO + bOff[g] + kx);
            }
            #pragma unroll
            for (int mt = 0; mt < 2; mt++)
                #pragma unroll
                for (int nt = 0; nt < 4; nt++) {
                    int g = nt >> 1, o = (nt & 1) * 2;
                    float* cc = cf[mt][nt];
                    MMA16816(cc, ah[mt], bh[g][o], bh[g][o+1]);
                    MMA16816(cc, ah[mt], bl[g][o], bl[g][o+1]);
                    MMA16816(cc, al[mt], bh[g][o], bh[g][o+1]);
                }
        }
        __syncthreads();
    }

    const int mrow = m0 + wm*32 + (lane >> 2);
    const int ncl = wn*32 + (lane & 3)*2;
    if (splitK) {
        float* pbase = partial + ((size_t)(dir*XP_SLICES + slice))*RWS*128;
        #pragma unroll
        for (int mt = 0; mt < 2; mt++)
            #pragma unroll
            for (int nt = 0; nt < 4; nt++) {
                int n = ncl + nt*8;
                #pragma unroll
                for (int half = 0; half < 2; half++) {
                    int m = mrow + mt*16 + half*8;
                    *(float2*)(pbase + (size_t)m*128 + n) =
                        make_float2(cf[mt][nt][half*2], cf[mt][nt][half*2+1]);
                }
            }
        return;
    }
    float* Cf = getCf(cfId, dir);
    #pragma unroll
    for (int mt = 0; mt < 2; mt++) {
        #pragma unroll
        for (int nt = 0; nt < 4; nt++) {
            int n = n0 + ncl + nt*8;
            if (n >= N) continue;
            #pragma unroll
            for (int half = 0; half < 2; half++) {
                int m = mrow + mt*16 + half*8;
                float v0 = cf[mt][nt][half*2+0];
                float v1 = cf[mt][nt][half*2+1];
                if (epi == 1) {
                    v0 += bias[n];   v1 += bias[n+1];
                    v0 = (v0 > 20.f) ? v0 : log1pf(__expf(v0));
                    v1 = (v1 > 20.f) ? v1 : log1pf(__expf(v1));
                }
                *(float2*)(Cf + (size_t)m*N + n) = make_float2(v0, v1);
            }
        }
    }
}

// ===========================================================================
// KERNEL B (R8, measured 269 TF/s): 128x64 tile, 256 threads (4Mx2N warps),
// 2 CTAs/SM.  Used for in_proj and out_proj (large-N shapes).
// ===========================================================================
#define STAGE256 49152
#define SMEM256 (2*STAGE256)

__device__ __forceinline__ void stage256(
    uint32_t stg,
    const bf16* __restrict__ Ahi, const bf16* __restrict__ Alo,
    const bf16* __restrict__ Whi, const bf16* __restrict__ Wlo,
    int m0, int n0, int k0, int lda, int ldw, int N, int K, int tid)
{
    #pragma unroll
    for (int t = 0; t < 4; t++) {
        int idx = tid + t*256;
        int row = idx >> 3, col = idx & 7;
        int kk = k0 + col*8;
        uint32_t soff = (uint32_t)(row*128 + ((col*16) ^ ((row & 7) << 4)));
        int v = (kk < K) ? 16 : 0;
        size_t go = (size_t)(m0+row)*lda + (v ? kk : 0);
        CP16(stg + soff,         Ahi + go, v);
        CP16(stg + 16384 + soff, Alo + go, v);
    }
    #pragma unroll
    for (int t = 0; t < 2; t++) {
        int idx = tid + t*256;
        int row = idx >> 3, col = idx & 7;
        int kk = k0 + col*8;
        uint32_t soff = (uint32_t)(row*128 + ((col*16) ^ ((row & 7) << 4)));
        int gn = n0 + row;
        int v = (gn < N && kk < K) ? 16 : 0;
        size_t go = (size_t)(v ? gn : 0)*ldw + (v ? kk : 0);
        CP16(stg + 32768 + soff, Whi + go, v);
        CP16(stg + 40960 + soff, Wlo + go, v);
    }
}

__global__ __launch_bounds__(256, 2)
void k_gemm256(int aId, int lda,
               const bf16* __restrict__ Whi0, const bf16* __restrict__ Wlo0,
               const bf16* __restrict__ Whi1, const bf16* __restrict__ Wlo1,
               int cfId, float* __restrict__ outp, int M, int N, int K)
{
    extern __shared__ __align__(1024) char smem[];
    const int dir = blockIdx.z;
    const bf16* Ahi = actA_hi(aId, dir);
    const bf16* Alo = actA_lo(aId, dir);
    const bf16* Whi = dir ? Whi1 : Whi0;
    const bf16* Wlo = dir ? Wlo1 : Wlo0;

    const uint32_t tb = smem_u32(smem);
    const int tid = threadIdx.x, lane = tid & 31, wid = tid >> 5;
    const int wm = wid & 3, wn = wid >> 2;
    const int m0 = blockIdx.y * 128;
    const int n0 = blockIdx.x * 64;

    const int l15 = lane & 15;
    const int a_kbx = (lane & 16) ? 16 : 0;
    const int b_nrow = (lane & 7) + ((lane & 16) ? 8 : 0);
    const int b_kbx = (lane & 8) ? 16 : 0;

    uint32_t aOff[2], aMsk[2];
    #pragma unroll
    for (int mt = 0; mt < 2; mt++) {
        int r = wm*32 + mt*16 + l15;
        aOff[mt] = r * 128;
        aMsk[mt] = (r & 7) << 4;
    }
    uint32_t bOff[2], bMsk[2];
    #pragma unroll
    for (int g = 0; g < 2; g++) {
        int r = wn*32 + g*16 + b_nrow;
        bOff[g] = r * 128;
        bMsk[g] = (r & 7) << 4;
    }

    float cf[2][4][4];
    #pragma unroll
    for (int i = 0; i < 2; i++)
        #pragma unroll
        for (int j = 0; j < 4; j++)
            #pragma unroll
            for (int q = 0; q < 4; q++) cf[i][j][q] = 0.f;

    const int nch = (K + GTK - 1) / GTK;
    stage256(tb, Ahi, Alo, Whi, Wlo, m0, n0, 0, lda, K, N, K, tid);
    CP_COMMIT();

    for (int ch = 0; ch < nch; ch++) {
        if (ch + 1 < nch) {
            stage256(tb + ((ch+1)&1)*STAGE256, Ahi, Alo, Whi, Wlo,
                     m0, n0, (ch+1)*GTK, lda, K, N, K, tid);
            CP_COMMIT();
            CP_WAIT1();
        } else {
            CP_WAIT0();
        }
        __syncthreads();

        const uint32_t AHI = tb + (ch&1)*STAGE256;
        const uint32_t ALO = AHI + 16384, BHI = AHI + 32768, BLO = AHI + 40960;
        #pragma unroll
        for (int ks = 0; ks < 4; ks++) {
            const int kb = ks * 32;
            uint32_t ah[2][4], al[2][4], bh[2][4], bl[2][4];
            #pragma unroll
            for (int mt = 0; mt < 2; mt++) {
                uint32_t kx = (uint32_t)(kb + a_kbx) ^ aMsk[mt];
                LDSM4(ah[mt], AHI + aOff[mt] + kx);
                LDSM4(al[mt], ALO + aOff[mt] + kx);
            }
            #pragma unroll
            for (int g = 0; g < 2; g++) {
                uint32_t kx = (uint32_t)(kb + b_kbx) ^ bMsk[g];
                LDSM4(bh[g], BHI + bOff[g] + kx);
                LDSM4(bl[g], BLO + bOff[g] + kx);
            }
            #pragma unroll
            for (int mt = 0; mt < 2; mt++)
                #pragma unroll
                for (int nt = 0; nt < 4; nt++) {
                    int g = nt >> 1, o = (nt & 1) * 2;
                    float* cc = cf[mt][nt];
                    MMA16816(cc, ah[mt], bh[g][o], bh[g][o+1]);
                    MMA16816(cc, ah[mt], bl[g][o], bl[g][o+1]);
                    MMA16816(cc, al[mt], bh[g][o], bh[g][o+1]);
                }
        }
        __syncthreads();
    }

    float* Cf = getCf(cfId, dir);
    const int mrow = m0 + wm*32 + (lane >> 2);
    const int ncl = wn*32 + (lane & 3)*2;
    #pragma unroll
    for (int mt = 0; mt < 2; mt++) {
        #pragma unroll
        for (int nt = 0; nt < 4; nt++) {
            int n = n0 + ncl + nt*8;
            if (n >= N) continue;
            #pragma unroll
            for (int half = 0; half < 2; half++) {
                int m = mrow + mt*16 + half*8;
                float v0 = cf[mt][nt][half*2+0];
                float v1 = cf[mt][nt][half*2+1];
                *(float2*)(Cf + (size_t)m*N + n) = make_float2(v0, v1);
                if (outp)
                    *(float2*)(outp + (size_t)m*(2*DM) + dir*DM + n) = make_float2(v0, v1);
            }
        }
    }
}

// ---------------------------------------------------------------------------
// x_proj split-K reduce -> g_dbl f32 + bf16 hi/lo
// ---------------------------------------------------------------------------
__global__ void k_xp_reduce() {
    int idx = blockIdx.x * blockDim.x + threadIdx.x;
    int dir = blockIdx.y;
    if (idx >= RWS*DBLW) return;
    int m = idx / DBLW, n = idx % DBLW;
    const float* p = g_xp_part[dir][0] + (size_t)m*128 + n;
    float s = 0.f;
    #pragma unroll
    for (int sl = 0; sl < XP_SLICES; sl++) s += p[(size_t)sl*RWS*128];
    g_dbl[dir][idx] = s;
    fsplit(s, &g_dbl_hi[dir][idx], &g_dbl_lo[dir][idx]);
}

// ---------------------------------------------------------------------------
// Conv1d (k=4) + bias + SiLU -> f32 + bf16 hi/lo
// ---------------------------------------------------------------------------
__global__ void k_conv(const float* __restrict__ cwF, const float* __restrict__ cwB,
                       const float* __restrict__ cbF, const float* __restrict__ cbB) {
    int idx = blockIdx.x * blockDim.x + threadIdx.x;
    int dir = blockIdx.y;
    if (idx >= RWS*DI) return;
    int row = idx / DI, c = idx % DI;
    int b = row / LSEQ, l = row % LSEQ;
    const float* cw = (dir ? cwB : cwF) + c*DC;
    float acc = (dir ? cbB : cbF)[c];
    const float* xz = g_xz[dir];
    #pragma unroll
    for (int k = 0; k < DC; k++) {
        int ls = l - (DC-1) + k;
        if (ls >= 0) acc += xz[((size_t)(b*LSEQ + ls))*2*DI + c] * cw[k];
    }
    float v = acc / (1.f + __expf(-acc));
    g_xc[dir][idx] = v;
    fsplit(v, &g_xc_hi[dir][idx], &g_xc_lo[dir][idx]);
}

// ---------------------------------------------------------------------------
// Selective scan + D-skip + silu(z) gating -> bf16 hi/lo y
// ---------------------------------------------------------------------------
#define SCAN_TD 128
#define TCH 64

__global__ __launch_bounds__(SCAN_TD)
void k_scan(const float* __restrict__ alF, const float* __restrict__ alB,
            const float* __restrict__ dpF, const float* __restrict__ dpB) {
    int dir = blockIdx.z;
    int b = blockIdx.y;
    int d = blockIdx.x * SCAN_TD + threadIdx.x;

    const float* Alog = (dir ? alB : alF) + (size_t)d * DS;
    float Arow[DS];
    bool fastA = true;
    #pragma unroll
    for (int n = 0; n < DS; n++) {
        Arow[n] = -__expf(Alog[n]);
        float tgt = -(float)(n+1);
        fastA = fastA && (fabsf(Arow[n] - tgt) <= 1e-4f * (float)(n+1));
    }
    float Dv = (dir ? dpB : dpF)[d];

    float h[DS];
    #pragma unroll
    for (int n = 0; n < DS; n++) h[n] = 0.f;

    __shared__ float sB[TCH][DS];
    __shared__ float sC[TCH][DS];

    const float* dbl  = g_dbl[dir];
    const float* delt = g_delta[dir];
    const float* xcb  = g_xc[dir];
    const float* xzb  = g_xz[dir];
    bf16* yh = g_y_hi[dir];
    bf16* yl = g_y_lo[dir];

    for (int t0 = 0; t0 < LSEQ; t0 += TCH) {
        for (int i = threadIdx.x; i < TCH*DS; i += SCAN_TD) {
            int tt = i / DS, n = i % DS;
            size_t r = (size_t)(b*LSEQ + t0 + tt);
            sB[tt][n] = dbl[r*DBLW + DTR + n];
            sC[tt][n] = dbl[r*DBLW + DTR + DS + n];
        }
        __syncthreads();
        if (fastA) {
            for (int tt = 0; tt < TCH; tt++) {
                size_t r = (size_t)(b*LSEQ + t0 + tt);
                float dv = delt[r*DI + d];
                float xv = xcb[r*DI + d];
                float du = dv * xv;
                float e1 = __expf(-dv);
                float p = e1;
                float y = 0.f;
                #pragma unroll
                for (int n = 0; n < DS; n++) {
                    h[n] = h[n]*p + du*sB[tt][n];
                    y += h[n]*sC[tt][n];
                    p *= e1;
                }
                float zv = xzb[r*2*DI + DI + d];
                float yv = (y + xv*Dv) * (zv / (1.f + __expf(-zv)));
                fsplit(yv, yh + r*DI + d, yl + r*DI + d);
            }
        } else {
            for (int tt = 0; tt < TCH; tt++) {
                size_t r = (size_t)(b*LSEQ + t0 + tt);
                float dv = delt[r*DI + d];
                float xv = xcb[r*DI + d];
                float du = dv * xv;
                float y = 0.f;
                #pragma unroll
                for (int n = 0; n < DS; n++) {
                    float e = __expf(dv * Arow[n]);
                    h[n] = h[n]*e + du*sB[tt][n];
                    y += h[n]*sC[tt][n];
                }
                float zv = xzb[r*2*DI + DI + d];
                float yv = (y + xv*Dv) * (zv / (1.f + __expf(-zv)));
                fsplit(yv, yh + r*DI + d, yl + r*DI + d);
            }
        }
        __syncthreads();
    }
}

// ---------------------------------------------------------------------------
// Host launcher
// ---------------------------------------------------------------------------
extern "C" void kernel_launch(void* const* d_in, const int* in_sizes, int n_in,
                              void* d_out, int out_size) {
    (void)in_sizes; (void)n_in; (void)out_size;
    const int* ids = (const int*)d_in[0];
    const float* F[11]; const float* Bw[11];
    for (int i = 0; i < 11; i++) {
        F[i]  = (const float*)d_in[1 + i];
        Bw[i] = (const float*)d_in[12 + i];
    }
    float* out = (float*)d_out;

    static int smem_set = 0;
    if (!smem_set) {
        cudaFuncSetAttribute(k_gemm512, cudaFuncAttributeMaxDynamicSharedMemorySize, SMEM512);
        cudaFuncSetAttribute(k_gemm256, cudaFuncAttributeMaxDynamicSharedMemorySize, SMEM256);
        smem_set = 1;
    }

    bf16 *wip_hi[2], *wip_lo[2], *wxp_hi[2], *wxp_lo[2];
    bf16 *wdt_hi[2], *wdt_lo[2], *wop_hi[2], *wop_lo[2];
    float* xp_part;
    {
        void* p;
        cudaGetSymbolAddress(&p, g_wip_hi); wip_hi[0]=(bf16*)p; wip_hi[1]=(bf16*)p + (size_t)NL*2*DI*DM;
        cudaGetSymbolAddress(&p, g_wip_lo); wip_lo[0]=(bf16*)p; wip_lo[1]=(bf16*)p + (size_t)NL*2*DI*DM;
        cudaGetSymbolAddress(&p, g_wxp_hi); wxp_hi[0]=(bf16*)p; wxp_hi[1]=(bf16*)p + (size_t)NL*DBLW*DI;
        cudaGetSymbolAddress(&p, g_wxp_lo); wxp_lo[0]=(bf16*)p; wxp_lo[1]=(bf16*)p + (size_t)NL*DBLW*DI;
        cudaGetSymbolAddress(&p, g_wdt_hi); wdt_hi[0]=(bf16*)p; wdt_hi[1]=(bf16*)p + (size_t)NL*DI*DTR;
        cudaGetSymbolAddress(&p, g_wdt_lo); wdt_lo[0]=(bf16*)p; wdt_lo[1]=(bf16*)p + (size_t)NL*DI*DTR;
        cudaGetSymbolAddress(&p, g_wop_hi); wop_hi[0]=(bf16*)p; wop_hi[1]=(bf16*)p + (size_t)NL*DM*DI;
        cudaGetSymbolAddress(&p, g_wop_lo); wop_lo[0]=(bf16*)p; wop_lo[1]=(bf16*)p + (size_t)NL*DM*DI;
        cudaGetSymbolAddress(&p, g_xp_part); xp_part = (float*)p;
    }

    // launches 1-3: weight splits; 4: embedding
    {
        int n4 = NL*2*DI*DM/4;
        k_wsplit<<<dim3((n4+255)/256, 2), 256>>>(
            (const float4*)F[2], (const float4*)Bw[2],
            (bf162*)wip_hi[0], (bf162*)wip_lo[0], (bf162*)wip_hi[1], (bf162*)wip_lo[1], n4);
    }
    {
        int n4 = NL*DM*DI/4;
        k_wsplit<<<dim3((n4+255)/256, 2), 256>>>(
            (const float4*)F[10], (const float4*)Bw[10],
            (bf162*)wop_hi[0], (bf162*)wop_lo[0], (bf162*)wop_hi[1], (bf162*)wop_lo[1], n4);
    }
    {
        int n40 = NL*DBLW*DI/4, n41 = NL*DI*DTR/4;
        int gx = ((n40 > n41 ? n40 : n41) + 255)/256;
        k_wsplit2<<<dim3(gx, 4), 256>>>(
            (const float4*)F[5], (const float4*)Bw[5],
            (bf162*)wxp_hi[0], (bf162*)wxp_lo[0], (bf162*)wxp_hi[1], (bf162*)wxp_lo[1], n40,
            (const float4*)F[6], (const float4*)Bw[6],
            (bf162*)wdt_hi[0], (bf162*)wdt_lo[0], (bf162*)wdt_hi[1], (bf162*)wdt_lo[1], n41);
    }
    k_embed<<<dim3(RWS, 2), 192>>>(ids, F[0], Bw[0]);

    for (int layer = 0; layer < NL; layer++) {
        const float* nwF = F[1]  + (size_t)layer*DM;
        const float* nwB = Bw[1] + (size_t)layer*DM;
        const float* cwF = F[3]  + (size_t)layer*DI*DC;
        const float* cwB = Bw[3] + (size_t)layer*DI*DC;
        const float* cbF = F[4]  + (size_t)layer*DI;
        const float* cbB = Bw[4] + (size_t)layer*DI;
        const float* dbF = F[7]  + (size_t)layer*DI;
        const float* dbB = Bw[7] + (size_t)layer*DI;
        const float* alF = F[8]  + (size_t)layer*DI*DS;
        const float* alB = Bw[8] + (size_t)layer*DI*DS;
        const float* dpF = F[9]  + (size_t)layer*DI;
        const float* dpB = Bw[9] + (size_t)layer*DI;

        size_t oip = (size_t)layer*2*DI*DM;
        size_t oxp = (size_t)layer*DBLW*DI;
        size_t odt = (size_t)layer*DI*DTR;
        size_t oop = (size_t)layer*DM*DI;

        // launch 5 (L0): rmsnorm
        k_rmsnorm<<<dim3(RWS, 2), 256>>>(nwF, nwB);

        // launch 6 (L0): in_proj (ncu capture target) — 128x64 2-CTA kernel
        k_gemm256<<<dim3(2*DI/64, RWS/128, 2), 256, SMEM256>>>(
            0, DM, wip_hi[0]+oip, wip_lo[0]+oip, wip_hi[1]+oip, wip_lo[1]+oip,
            1, nullptr, RWS, 2*DI, DM);

        // conv + split
        k_conv<<<dim3(RWS*DI/256, 2), 256>>>(cwF, cwB, cbF, cbB);

        // x_proj split-K=8 (R6 config, 512t kernel)
        k_gemm512<<<dim3(XP_SLICES, RWS/128, 2), 512, SMEM512>>>(
            1, DI, wxp_hi[0]+oxp, wxp_lo[0]+oxp, wxp_hi[1]+oxp, wxp_lo[1]+oxp,
            0, RWS, DBLW, DI, nullptr, nullptr, 0, 1, xp_part);
        k_xp_reduce<<<dim3((RWS*DBLW+255)/256, 2), 256>>>();

        // delta (R6 config, 512t kernel, softplus epi)
        k_gemm512<<<dim3(DI/128, RWS/128, 2), 512, SMEM512>>>(
            2, DBLW, wdt_hi[0]+odt, wdt_lo[0]+odt, wdt_hi[1]+odt, wdt_lo[1]+odt,
            4, RWS, DI, DTR, dbF, dbB, 1, 0, nullptr);

        k_scan<<<dim3(DI/SCAN_TD, BSZ, 2), SCAN_TD>>>(alF, alB, dpF, dpB);

        // out_proj — 128x64 2-CTA kernel, fused d_out write
        k_gemm256<<<dim3(DM/64, RWS/128, 2), 256, SMEM256>>>(
            3, DI, wop_hi[0]+oop, wop_lo[0]+oop, wop_hi[1]+oop, wop_lo[1]+oop,
            6, out + (size_t)layer*RWS*2*DM, RWS, DM, DI);
    }
}